// round 3
// baseline (speedup 1.0000x reference)
#include <cuda_runtime.h>
#include <cuda_bf16.h>
#include <math.h>

// ---------------- problem constants ----------------
#define TT 1024
#define HH 2048
#define NHEAD 16
#define NKVH 4
#define HD 128
#define NEXP 16
#define II 768
#define QKVN 3072   // (16+8)*128
#define EPSV 1e-6f

// ---------------- device scratch (no allocs allowed) ----------------
__device__ float g_h1[TT*HH];
__device__ float g_qkv[TT*QKVN];
__device__ float g_q[TT*NHEAD*HD];
__device__ float g_k[TT*NKVH*HD];
__device__ float g_v[TT*NKVH*HD];
__device__ float g_ctx[TT*HH];
__device__ float g_h2[TT*HH];
__device__ int   g_topi[TT*2];
__device__ float g_topw[TT*2];
__device__ int   g_list[NEXP*TT];
__device__ int   g_count[NEXP];
__device__ float g_gbuf[NEXP*TT*II];   // silu(gate)
__device__ float g_ubuf[NEXP*TT*II];   // up
__device__ float g_yslot[TT*2*HH];

// ---------------- rmsnorm over 2048 ----------------
__global__ void rmsnorm_kernel(const float* __restrict__ x, const float* __restrict__ w,
                               float* __restrict__ out) {
    int t = blockIdx.x;
    const float* row = x + (size_t)t*HH;
    float ss = 0.f;
    for (int j = threadIdx.x; j < HH; j += 256) { float v = row[j]; ss += v*v; }
    __shared__ float sred[256];
    sred[threadIdx.x] = ss; __syncthreads();
    for (int s = 128; s > 0; s >>= 1) {
        if (threadIdx.x < s) sred[threadIdx.x] += sred[threadIdx.x+s];
        __syncthreads();
    }
    float scale = rsqrtf(sred[0]/(float)HH + EPSV);
    for (int j = threadIdx.x; j < HH; j += 256)
        out[(size_t)t*HH + j] = row[j]*scale*w[j];
}

// ---------------- generic SGEMM 128x128x8, 8x8 per thread ----------------
// A: MxK row-major, B: KxN row-major, C = A@B (+ addend)
__global__ void sgemm_kernel(const float* __restrict__ A, const float* __restrict__ B,
                             float* __restrict__ C, int M, int N, int K,
                             const float* __restrict__ addend) {
    __shared__ float As[8][128];
    __shared__ float Bs[8][128];
    int tid = threadIdx.x;
    int bx = blockIdx.x * 128, by = blockIdx.y * 128;
    int tx = tid & 15, ty = tid >> 4;
    float acc[8][8];
    #pragma unroll
    for (int i=0;i<8;i++)
        #pragma unroll
        for (int j=0;j<8;j++) acc[i][j]=0.f;
    int a_m = tid >> 3, a_k = tid & 7;       // row 0..31, col 0..7
    int b_k = tid >> 7, b_n = tid & 127;     // row 0..1,  col 0..127
    for (int k0 = 0; k0 < K; k0 += 8) {
        #pragma unroll
        for (int i = 0; i < 4; i++) {
            int m = a_m + i*32;
            As[a_k][m] = A[(size_t)(by+m)*K + k0+a_k];
        }
        #pragma unroll
        for (int i = 0; i < 4; i++) {
            int kk = b_k + i*2;
            Bs[kk][b_n] = B[(size_t)(k0+kk)*N + bx+b_n];
        }
        __syncthreads();
        #pragma unroll
        for (int kk = 0; kk < 8; kk++) {
            float a[8], b[8];
            #pragma unroll
            for (int i=0;i<8;i++) a[i] = As[kk][ty*8+i];
            #pragma unroll
            for (int j=0;j<8;j++) b[j] = Bs[kk][tx*8+j];
            #pragma unroll
            for (int i=0;i<8;i++)
                #pragma unroll
                for (int j=0;j<8;j++) acc[i][j] += a[i]*b[j];
        }
        __syncthreads();
    }
    #pragma unroll
    for (int i=0;i<8;i++) {
        int m = by + ty*8+i;
        #pragma unroll
        for (int j=0;j<8;j++) {
            int n = bx + tx*8+j;
            float v = acc[i][j];
            if (addend) v += addend[(size_t)m*N+n];
            C[(size_t)m*N+n] = v;
        }
    }
}

// ---------------- per-(token,head) qk rmsnorm + rope; v copy ----------------
__global__ void qkv_post_kernel(const int* __restrict__ pos,
                                const float* __restrict__ wq, const float* __restrict__ wk) {
    int t = blockIdx.y;
    int slot = blockIdx.x; // 0..15 q heads, 16..19 k heads, 20..23 v heads
    int d = threadIdx.x;   // 128
    const float* src;
    if (slot < 16)       src = g_qkv + (size_t)t*QKVN + slot*HD;
    else if (slot < 20)  src = g_qkv + (size_t)t*QKVN + 2048 + (slot-16)*HD;
    else                 src = g_qkv + (size_t)t*QKVN + 2560 + (slot-20)*HD;
    float v = src[d];
    if (slot >= 20) { g_v[(size_t)t*NKVH*HD + (slot-20)*HD + d] = v; return; }
    float x2 = v*v;
    #pragma unroll
    for (int o=16;o;o>>=1) x2 += __shfl_xor_sync(0xffffffffu, x2, o);
    __shared__ float wsum[4];
    if ((d&31)==0) wsum[d>>5] = x2;
    __syncthreads();
    float tot = wsum[0]+wsum[1]+wsum[2]+wsum[3];
    float scale = rsqrtf(tot/(float)HD + EPSV);
    const float* wn = (slot<16)? wq : wk;
    float xn = v * scale * wn[d];
    __shared__ float sh[128];
    sh[d] = xn; __syncthreads();
    int i = d & 63;
    float inv = expf(-(float)i * (logf(10000.0f)/64.0f));
    float ang = (float)pos[t] * inv;
    float c = cosf(ang), s = sinf(ang);
    float o;
    if (d < 64) o = sh[d]*c - sh[d+64]*s;
    else        o = sh[d]*c + sh[d-64]*s;
    if (slot < 16) g_q[(size_t)t*NHEAD*HD + slot*HD + d] = o * 0.08838834764831845f; // fold 1/sqrt(HD)
    else           g_k[(size_t)t*NKVH*HD + (slot-16)*HD + d] = o;
}

// ---------------- flash-style attention, 64 q-rows per block ----------------
#define QS_STRIDE 132
#define S_STRIDE  66
__global__ void attn_kernel() {
    extern __shared__ float sm[];
    float* Qs   = sm;                      // 64*132
    float* KV   = Qs + 64*QS_STRIDE;       // 64*132
    float* S    = KV + 64*QS_STRIDE;       // 64*66
    float* mrow = S + 64*S_STRIDE;
    float* lrow = mrow + 64;
    float* arow = lrow + 64;
    int h = blockIdx.x, qt = blockIdx.y;
    int kvh = h >> 2;
    int tid = threadIdx.x;
    int r = tid >> 2, g = tid & 3;     // load/softmax mapping
    int tr = tid >> 4, tc = tid & 15;  // compute mapping
    {
        const float* src = g_q + (size_t)(qt*64 + r)*HH + h*HD + g*32;
        float* dst = Qs + r*QS_STRIDE + g*32;
        #pragma unroll
        for (int i=0;i<32;i++) dst[i] = src[i];
    }
    if (tid < 64) { mrow[tid] = -1e30f; lrow[tid] = 0.f; }
    float O[4][8];
    #pragma unroll
    for (int i=0;i<4;i++)
        #pragma unroll
        for (int j=0;j<8;j++) O[i][j]=0.f;
    __syncthreads();
    for (int kt = 0; kt < 16; kt++) {
        { // K tile
            const float* src = g_k + (size_t)(kt*64 + r)*NKVH*HD + kvh*HD + g*32;
            float* dst = KV + r*QS_STRIDE + g*32;
            #pragma unroll
            for (int i=0;i<32;i++) dst[i] = src[i];
        }
        __syncthreads();
        { // S = Q K^T (4x4 per thread)
            float acc[4][4];
            #pragma unroll
            for (int i=0;i<4;i++)
                #pragma unroll
                for (int j=0;j<4;j++) acc[i][j]=0.f;
            for (int d=0; d<HD; d++) {
                float a[4], b[4];
                #pragma unroll
                for (int i=0;i<4;i++) a[i] = Qs[(4*tr+i)*QS_STRIDE + d];
                #pragma unroll
                for (int j=0;j<4;j++) b[j] = KV[(4*tc+j)*QS_STRIDE + d];
                #pragma unroll
                for (int i=0;i<4;i++)
                    #pragma unroll
                    for (int j=0;j<4;j++) acc[i][j] += a[i]*b[j];
            }
            #pragma unroll
            for (int i=0;i<4;i++)
                #pragma unroll
                for (int j=0;j<4;j++) S[(4*tr+i)*S_STRIDE + 4*tc+j] = acc[i][j];
        }
        __syncthreads();
        { // online softmax update, then load V tile
            float* Sr = S + r*S_STRIDE + g*16;
            float mloc = -1e30f;
            #pragma unroll
            for (int j=0;j<16;j++) mloc = fmaxf(mloc, Sr[j]);
            #pragma unroll
            for (int o=1;o<4;o<<=1) mloc = fmaxf(mloc, __shfl_xor_sync(0xffffffffu, mloc, o));
            float mold = mrow[r];
            float mnew = fmaxf(mold, mloc);
            float psum = 0.f;
            #pragma unroll
            for (int j=0;j<16;j++) { float pp = expf(Sr[j]-mnew); Sr[j]=pp; psum+=pp; }
            #pragma unroll
            for (int o=1;o<4;o<<=1) psum += __shfl_xor_sync(0xffffffffu, psum, o);
            if (g==0) {
                float alpha = expf(mold - mnew);
                arow[r] = alpha;
                mrow[r] = mnew;
                lrow[r] = lrow[r]*alpha + psum;
            }
            const float* src = g_v + (size_t)(kt*64 + r)*NKVH*HD + kvh*HD + g*32;
            float* dst = KV + r*QS_STRIDE + g*32;
            #pragma unroll
            for (int i=0;i<32;i++) dst[i] = src[i];
        }
        __syncthreads();
        { // rescale O, accumulate P@V
            float al[4];
            #pragma unroll
            for (int i=0;i<4;i++) al[i] = arow[4*tr+i];
            #pragma unroll
            for (int i=0;i<4;i++)
                #pragma unroll
                for (int j=0;j<8;j++) O[i][j]*=al[i];
            for (int kk=0; kk<64; kk++) {
                float b[8];
                #pragma unroll
                for (int j=0;j<8;j++) b[j] = KV[kk*QS_STRIDE + tc*8 + j];
                #pragma unroll
                for (int i=0;i<4;i++) {
                    float pv = S[(4*tr+i)*S_STRIDE + kk];
                    #pragma unroll
                    for (int j=0;j<8;j++) O[i][j] += pv*b[j];
                }
            }
        }
        __syncthreads();
    }
    #pragma unroll
    for (int i=0;i<4;i++) {
        int row = 4*tr+i;
        float linv = 1.0f / lrow[row];
        float* dst = g_ctx + (size_t)(qt*64+row)*HH + h*HD + tc*8;
        #pragma unroll
        for (int j=0;j<8;j++) dst[j] = O[i][j]*linv;
    }
}

// ---------------- router: logits, top-2, normalized weights ----------------
__global__ void router_kernel(const float* __restrict__ wr) {
    int t = blockIdx.x;
    float acc[NEXP];
    #pragma unroll
    for (int e=0;e<NEXP;e++) acc[e]=0.f;
    for (int j=threadIdx.x; j<HH; j+=256) {
        float x = g_h2[(size_t)t*HH+j];
        const float* w = wr + j*NEXP;
        #pragma unroll
        for (int e=0;e<NEXP;e++) acc[e] += x*w[e];
    }
    __shared__ float sred[256];
    __shared__ float logits[NEXP];
    for (int e=0;e<NEXP;e++) {
        sred[threadIdx.x]=acc[e]; __syncthreads();
        for (int s=128;s>0;s>>=1){ if(threadIdx.x<s) sred[threadIdx.x]+=sred[threadIdx.x+s]; __syncthreads(); }
        if (threadIdx.x==0) logits[e]=sred[0];
        __syncthreads();
    }
    if (threadIdx.x==0) {
        int i1=0; float l1=logits[0];
        for (int e=1;e<NEXP;e++) if (logits[e]>l1){l1=logits[e]; i1=e;}
        int i2=-1; float l2=-1e30f;
        for (int e=0;e<NEXP;e++) if (e!=i1 && logits[e]>l2){l2=logits[e]; i2=e;}
        float w1 = 1.0f/(1.0f+expf(l2-l1));
        g_topi[2*t]=i1; g_topi[2*t+1]=i2;
        g_topw[2*t]=w1; g_topw[2*t+1]=1.0f-w1;
    }
}

// ---------------- deterministic per-expert compaction (block scan) ----------------
__global__ void build_lists_kernel() {
    int e = blockIdx.x;
    int t = threadIdx.x; // 1024 threads
    int slot = -1;
    if (g_topi[2*t]==e) slot=0; else if (g_topi[2*t+1]==e) slot=1;
    int flag = (slot>=0) ? 1 : 0;
    unsigned mask = __ballot_sync(0xffffffffu, flag);
    int lane = t & 31, warp = t >> 5;
    int pos = __popc(mask & ((1u<<lane)-1u));
    __shared__ int wsum[32];
    if (lane==0) wsum[warp]=__popc(mask);
    __syncthreads();
    if (t < 32) {
        int v = wsum[t];
        #pragma unroll
        for (int o=1;o<32;o<<=1){ int n=__shfl_up_sync(0xffffffffu, v, o); if (t>=o) v+=n; }
        wsum[t]=v; // inclusive
    }
    __syncthreads();
    int base = (warp==0) ? 0 : wsum[warp-1];
    if (flag) g_list[e*TT + base + pos] = 2*t+slot;
    if (t==0) g_count[e]=wsum[31];
}

// ---------------- expert gate/up GEMM (rows gathered via list) ----------------
__global__ void expert_gu_kernel(const float* __restrict__ W, float* __restrict__ out,
                                 int applySilu) {
    int e = blockIdx.z;
    int cnt = g_count[e];
    int by = blockIdx.y * 128;
    if (by >= cnt) return;
    int bx = blockIdx.x * 128;  // N = 768
    __shared__ float As[8][128];
    __shared__ float Bs[8][128];
    __shared__ int rows[128];
    int tid = threadIdx.x;
    if (tid < 128) {
        int idx = by + tid;
        rows[tid] = (idx < cnt) ? (g_list[e*TT + idx] >> 1) : 0;
    }
    __syncthreads();
    const float* Wb = W + (size_t)e * HH * II;
    int tx = tid & 15, ty = tid >> 4;
    float acc[8][8];
    #pragma unroll
    for (int i=0;i<8;i++)
        #pragma unroll
        for (int j=0;j<8;j++) acc[i][j]=0.f;
    int a_m = tid >> 3, a_k = tid & 7;
    int b_k = tid >> 7, b_n = tid & 127;
    for (int k0 = 0; k0 < HH; k0 += 8) {
        #pragma unroll
        for (int i=0;i<4;i++) {
            int m = a_m + i*32;
            As[a_k][m] = g_h2[(size_t)rows[m]*HH + k0 + a_k];
        }
        #pragma unroll
        for (int i=0;i<4;i++) {
            int kk = b_k + i*2;
            Bs[kk][b_n] = Wb[(size_t)(k0+kk)*II + bx + b_n];
        }
        __syncthreads();
        #pragma unroll
        for (int kk=0;kk<8;kk++) {
            float a[8], b[8];
            #pragma unroll
            for (int i=0;i<8;i++) a[i]=As[kk][ty*8+i];
            #pragma unroll
            for (int j=0;j<8;j++) b[j]=Bs[kk][tx*8+j];
            #pragma unroll
            for (int i=0;i<8;i++)
                #pragma unroll
                for (int j=0;j<8;j++) acc[i][j] += a[i]*b[j];
        }
        __syncthreads();
    }
    #pragma unroll
    for (int i=0;i<8;i++) {
        int m = by + ty*8 + i;
        if (m < cnt) {
            float* dst = out + ((size_t)e*TT + m)*II + bx + tx*8;
            #pragma unroll
            for (int j=0;j<8;j++) {
                float v = acc[i][j];
                if (applySilu) v = v / (1.0f + expf(-v));
                dst[j] = v;
            }
        }
    }
}

// ---------------- expert down GEMM: (silu(g)*u) @ Wd -> yslot ----------------
__global__ void expert_down_kernel(const float* __restrict__ Wd) {
    int e = blockIdx.z;
    int cnt = g_count[e];
    int by = blockIdx.y * 128;
    if (by >= cnt) return;
    int bx = blockIdx.x * 128;  // N = 2048
    __shared__ float As[8][128];
    __shared__ float Bs[8][128];
    int tid = threadIdx.x;
    int tx = tid & 15, ty = tid >> 4;
    float acc[8][8];
    #pragma unroll
    for (int i=0;i<8;i++)
        #pragma unroll
        for (int j=0;j<8;j++) acc[i][j]=0.f;
    const float* Wb = Wd + (size_t)e*II*HH;
    size_t base = (size_t)e*TT + by;
    int a_m = tid >> 3, a_k = tid & 7;
    int b_k = tid >> 7, b_n = tid & 127;
    for (int k0=0;k0<II;k0+=8) {
        #pragma unroll
        for (int i=0;i<4;i++) {
            int m = a_m + i*32;
            size_t off = (base+m)*II + k0+a_k;
            As[a_k][m] = g_gbuf[off]*g_ubuf[off];
        }
        #pragma unroll
        for (int i=0;i<4;i++) {
            int kk = b_k + i*2;
            Bs[kk][b_n] = Wb[(size_t)(k0+kk)*HH + bx+b_n];
        }
        __syncthreads();
        #pragma unroll
        for (int kk=0;kk<8;kk++) {
            float a[8], b[8];
            #pragma unroll
            for (int i=0;i<8;i++) a[i]=As[kk][ty*8+i];
            #pragma unroll
            for (int j=0;j<8;j++) b[j]=Bs[kk][tx*8+j];
            #pragma unroll
            for (int i=0;i<8;i++)
                #pragma unroll
                for (int j=0;j<8;j++) acc[i][j] += a[i]*b[j];
        }
        __syncthreads();
    }
    #pragma unroll
    for (int i=0;i<8;i++) {
        int m = by + ty*8 + i;
        if (m < cnt) {
            int entry = g_list[e*TT + m];
            float* dst = g_yslot + (size_t)entry*HH + bx + tx*8;
            #pragma unroll
            for (int j=0;j<8;j++) dst[j] = acc[i][j];
        }
    }
}

// ---------------- final combine ----------------
__global__ void combine_kernel(float* __restrict__ out) {
    int t = blockIdx.x;
    float w0 = g_topw[2*t], w1 = g_topw[2*t+1];
    const float* y0 = g_yslot + (size_t)(2*t)*HH;
    const float* y1 = y0 + HH;
    float* o = out + (size_t)t*HH;
    for (int j=threadIdx.x;j<HH;j+=256) o[j] = w0*y0[j] + w1*y1[j];
}

// ---------------- launch ----------------
extern "C" void kernel_launch(void* const* d_in, const int* in_sizes, int n_in,
                              void* d_out, int out_size) {
    const float* hidden   = (const float*)d_in[0];
    const int*   pos      = (const int*)  d_in[1];
    const float* w_norm1  = (const float*)d_in[2];
    const float* w_norm2  = (const float*)d_in[3];
    const float* w_qkv    = (const float*)d_in[4];
    const float* w_qnorm  = (const float*)d_in[5];
    const float* w_knorm  = (const float*)d_in[6];
    const float* w_o      = (const float*)d_in[7];
    const float* w_router = (const float*)d_in[8];
    const float* w_gate   = (const float*)d_in[9];
    const float* w_up     = (const float*)d_in[10];
    const float* w_down   = (const float*)d_in[11];
    (void)in_sizes; (void)n_in; (void)out_size;

    float* moe_out = (float*)d_out;
    float* resid   = (float*)d_out + (size_t)TT*HH;

    void* p;
    cudaGetSymbolAddress(&p, g_h1);   float* h1   = (float*)p;
    cudaGetSymbolAddress(&p, g_qkv);  float* qkv  = (float*)p;
    cudaGetSymbolAddress(&p, g_ctx);  float* ctx  = (float*)p;
    cudaGetSymbolAddress(&p, g_h2);   float* h2   = (float*)p;
    cudaGetSymbolAddress(&p, g_gbuf); float* gbuf = (float*)p;
    cudaGetSymbolAddress(&p, g_ubuf); float* ubuf = (float*)p;

    int attn_smem = (64*QS_STRIDE*2 + 64*S_STRIDE + 192) * 4;
    cudaFuncSetAttribute(attn_kernel, cudaFuncAttributeMaxDynamicSharedMemorySize, attn_smem);

    rmsnorm_kernel<<<TT, 256>>>(hidden, w_norm1, h1);
    sgemm_kernel<<<dim3(QKVN/128, TT/128), 256>>>(h1, w_qkv, qkv, TT, QKVN, HH, nullptr);
    qkv_post_kernel<<<dim3(24, TT), 128>>>(pos, w_qnorm, w_knorm);
    attn_kernel<<<dim3(NHEAD, TT/64), 256, attn_smem>>>();
    sgemm_kernel<<<dim3(HH/128, TT/128), 256>>>(ctx, w_o, resid, TT, HH, HH, hidden);
    rmsnorm_kernel<<<TT, 256>>>(resid, w_norm2, h2);
    router_kernel<<<TT, 256>>>(w_router);
    build_lists_kernel<<<NEXP, TT>>>();
    expert_gu_kernel<<<dim3(II/128, TT/128, NEXP), 256>>>(w_gate, gbuf, 1);
    expert_gu_kernel<<<dim3(II/128, TT/128, NEXP), 256>>>(w_up, ubuf, 0);
    expert_down_kernel<<<dim3(HH/128, TT/128, NEXP), 256>>>(w_down);
    combine_kernel<<<TT, 256>>>(moe_out);
}

// round 8
// speedup vs baseline: 1.5270x; 1.5270x over previous
#include <cuda_runtime.h>
#include <cuda_bf16.h>
#include <math.h>

// ---------------- problem constants ----------------
#define TT 1024
#define HH 2048
#define NHEAD 16
#define NKVH 4
#define HD 128
#define NEXP 16
#define II 768
#define QKVN 3072   // (16+8)*128
#define EPSV 1e-6f

// ---------------- device scratch (no allocs allowed) ----------------
__device__ float g_h1[TT*HH];
__device__ float g_qkv[TT*QKVN];
__device__ float g_q[TT*NHEAD*HD];
__device__ float g_k[TT*NKVH*HD];
__device__ float g_v[TT*NKVH*HD];
__device__ float g_ctx[TT*HH];
__device__ float g_h2[TT*HH];
__device__ int   g_topi[TT*2];
__device__ float g_topw[TT*2];
__device__ int   g_list[NEXP*TT];
__device__ int   g_count[NEXP];
__device__ float g_gbuf[NEXP*TT*II];   // silu(gate)
__device__ float g_ubuf[NEXP*TT*II];   // up
__device__ float g_yslot[TT*2*HH];

// ---------------- rmsnorm over 2048 ----------------
__global__ void rmsnorm_kernel(const float* __restrict__ x, const float* __restrict__ w,
                               float* __restrict__ out) {
    int t = blockIdx.x;
    const float* row = x + (size_t)t*HH;
    float ss = 0.f;
    for (int j = threadIdx.x; j < HH; j += 256) { float v = row[j]; ss += v*v; }
    __shared__ float sred[256];
    sred[threadIdx.x] = ss; __syncthreads();
    for (int s = 128; s > 0; s >>= 1) {
        if (threadIdx.x < s) sred[threadIdx.x] += sred[threadIdx.x+s];
        __syncthreads();
    }
    float scale = rsqrtf(sred[0]/(float)HH + EPSV);
    for (int j = threadIdx.x; j < HH; j += 256)
        out[(size_t)t*HH + j] = row[j]*scale*w[j];
}

// ============= SGEMM: 128x128 tile, K-tile 16, double-buffered, float4 =============
// A: MxK row-major, B: KxN row-major, C = A@B (+ addend). K%16==0, N%128==0.
__global__ void __launch_bounds__(256) sgemm16_kernel(
        const float* __restrict__ A, const float* __restrict__ B,
        float* __restrict__ C, int M, int N, int K,
        const float* __restrict__ addend) {
    __shared__ float As[2][16][132];
    __shared__ float Bs[2][16][128];
    int tid = threadIdx.x;
    int bx = blockIdx.x * 128, by = blockIdx.y * 128;
    int tx = tid & 15, ty = tid >> 4;
    int a_row = tid >> 1, a_h = (tid & 1) * 8;
    int b_kr = tid >> 4, b_c = (tid & 15) * 8;

    float acc[8][8];
    #pragma unroll
    for (int i=0;i<8;i++)
        #pragma unroll
        for (int j=0;j<8;j++) acc[i][j]=0.f;

    float4 pa0, pa1, pb0, pb1;
    {
        const float4* ap = (const float4*)&A[(size_t)(by+a_row)*K + a_h];
        pa0 = ap[0]; pa1 = ap[1];
        const float4* bp = (const float4*)&B[(size_t)b_kr*N + bx + b_c];
        pb0 = bp[0]; pb1 = bp[1];
        As[0][a_h+0][a_row]=pa0.x; As[0][a_h+1][a_row]=pa0.y;
        As[0][a_h+2][a_row]=pa0.z; As[0][a_h+3][a_row]=pa0.w;
        As[0][a_h+4][a_row]=pa1.x; As[0][a_h+5][a_row]=pa1.y;
        As[0][a_h+6][a_row]=pa1.z; As[0][a_h+7][a_row]=pa1.w;
        *(float4*)&Bs[0][b_kr][b_c]   = pb0;
        *(float4*)&Bs[0][b_kr][b_c+4] = pb1;
    }
    __syncthreads();

    int ntiles = K >> 4;
    for (int kt = 0; kt < ntiles; kt++) {
        int cur = kt & 1, nxt = cur ^ 1;
        if (kt+1 < ntiles) {
            int k0 = (kt+1) << 4;
            const float4* ap = (const float4*)&A[(size_t)(by+a_row)*K + k0 + a_h];
            pa0 = ap[0]; pa1 = ap[1];
            const float4* bp = (const float4*)&B[(size_t)(k0+b_kr)*N + bx + b_c];
            pb0 = bp[0]; pb1 = bp[1];
        }
        #pragma unroll
        for (int kk = 0; kk < 16; kk++) {
            float4 a0 = *(const float4*)&As[cur][kk][ty*8];
            float4 a1 = *(const float4*)&As[cur][kk][ty*8+4];
            float4 b0 = *(const float4*)&Bs[cur][kk][tx*8];
            float4 b1 = *(const float4*)&Bs[cur][kk][tx*8+4];
            float a[8] = {a0.x,a0.y,a0.z,a0.w,a1.x,a1.y,a1.z,a1.w};
            float b[8] = {b0.x,b0.y,b0.z,b0.w,b1.x,b1.y,b1.z,b1.w};
            #pragma unroll
            for (int i=0;i<8;i++)
                #pragma unroll
                for (int j=0;j<8;j++) acc[i][j] += a[i]*b[j];
        }
        if (kt+1 < ntiles) {
            As[nxt][a_h+0][a_row]=pa0.x; As[nxt][a_h+1][a_row]=pa0.y;
            As[nxt][a_h+2][a_row]=pa0.z; As[nxt][a_h+3][a_row]=pa0.w;
            As[nxt][a_h+4][a_row]=pa1.x; As[nxt][a_h+5][a_row]=pa1.y;
            As[nxt][a_h+6][a_row]=pa1.z; As[nxt][a_h+7][a_row]=pa1.w;
            *(float4*)&Bs[nxt][b_kr][b_c]   = pb0;
            *(float4*)&Bs[nxt][b_kr][b_c+4] = pb1;
        }
        __syncthreads();
    }
    #pragma unroll
    for (int i=0;i<8;i++) {
        int m = by + ty*8+i;
        float* crow = C + (size_t)m*N + bx + tx*8;
        float4 v0 = make_float4(acc[i][0],acc[i][1],acc[i][2],acc[i][3]);
        float4 v1 = make_float4(acc[i][4],acc[i][5],acc[i][6],acc[i][7]);
        if (addend) {
            const float4* ad = (const float4*)(addend + (size_t)m*N + bx + tx*8);
            float4 d0 = ad[0], d1 = ad[1];
            v0.x+=d0.x; v0.y+=d0.y; v0.z+=d0.z; v0.w+=d0.w;
            v1.x+=d1.x; v1.y+=d1.y; v1.z+=d1.z; v1.w+=d1.w;
        }
        *(float4*)crow = v0;
        *(float4*)(crow+4) = v1;
    }
}

// ---------------- per-(token,head) qk rmsnorm + rope; v copy ----------------
__global__ void qkv_post_kernel(const int* __restrict__ pos,
                                const float* __restrict__ wq, const float* __restrict__ wk) {
    int t = blockIdx.y;
    int slot = blockIdx.x; // 0..15 q heads, 16..19 k heads, 20..23 v heads
    int d = threadIdx.x;   // 128
    const float* src;
    if (slot < 16)       src = g_qkv + (size_t)t*QKVN + slot*HD;
    else if (slot < 20)  src = g_qkv + (size_t)t*QKVN + 2048 + (slot-16)*HD;
    else                 src = g_qkv + (size_t)t*QKVN + 2560 + (slot-20)*HD;
    float v = src[d];
    if (slot >= 20) { g_v[(size_t)t*NKVH*HD + (slot-20)*HD + d] = v; return; }
    float x2 = v*v;
    #pragma unroll
    for (int o=16;o;o>>=1) x2 += __shfl_xor_sync(0xffffffffu, x2, o);
    __shared__ float wsum[4];
    if ((d&31)==0) wsum[d>>5] = x2;
    __syncthreads();
    float tot = wsum[0]+wsum[1]+wsum[2]+wsum[3];
    float scale = rsqrtf(tot/(float)HD + EPSV);
    const float* wn = (slot<16)? wq : wk;
    float xn = v * scale * wn[d];
    __shared__ float sh[128];
    sh[d] = xn; __syncthreads();
    int i = d & 63;
    float inv = expf(-(float)i * (logf(10000.0f)/64.0f));
    float ang = (float)pos[t] * inv;
    float c = cosf(ang), s = sinf(ang);
    float o;
    if (d < 64) o = sh[d]*c - sh[d+64]*s;
    else        o = sh[d]*c + sh[d-64]*s;
    if (slot < 16) g_q[(size_t)t*NHEAD*HD + slot*HD + d] = o * 0.08838834764831845f; // fold 1/sqrt(HD)
    else           g_k[(size_t)t*NKVH*HD + (slot-16)*HD + d] = o;
}

// ---------------- flash-style attention, 64 q-rows per block ----------------
// Q and K tiles stored d-major (transposed) in smem so the S=QK^T phase does
// contiguous LDS.128 instead of 8-way-conflicted scalar column loads.
#define QT_STRIDE 68    // Qt/Kt: [128 d][64 rows + pad]
#define V_STRIDE  132   // V: [64 keys][128 d + pad]
#define S_STRIDE  66
__global__ void __launch_bounds__(256) attn_kernel() {
    extern __shared__ float sm[];
    float* Qt   = sm;                    // 128*68 = 8704
    float* KV   = sm + 128*QT_STRIDE;    // 8704 (Kt [128][68] or V [64][132])
    float* S    = KV + 128*QT_STRIDE;    // 64*66
    float* mrow = S + 64*S_STRIDE;
    float* lrow = mrow + 64;
    float* arow = lrow + 64;
    int h = blockIdx.x, qt = blockIdx.y;
    int kvh = h >> 2;
    int tid = threadIdx.x;
    int r = tid >> 2, g = tid & 3;     // loader/softmax mapping: row r, quarter g
    int tr = tid >> 4, tc = tid & 15;  // compute mapping
    { // Q tile load, transposed store
        const float4* src = (const float4*)(g_q + (size_t)(qt*64 + r)*HH + h*HD + g*32);
        #pragma unroll
        for (int i4=0;i4<8;i4++) {
            float4 v = src[i4];
            int db = g*32 + i4*4;
            Qt[(db+0)*QT_STRIDE + r] = v.x;
            Qt[(db+1)*QT_STRIDE + r] = v.y;
            Qt[(db+2)*QT_STRIDE + r] = v.z;
            Qt[(db+3)*QT_STRIDE + r] = v.w;
        }
    }
    if (tid < 64) { mrow[tid] = -1e30f; lrow[tid] = 0.f; }
    float O[4][8];
    #pragma unroll
    for (int i=0;i<4;i++)
        #pragma unroll
        for (int j=0;j<8;j++) O[i][j]=0.f;
    __syncthreads();
    for (int kt = 0; kt < 16; kt++) {
        { // K tile, transposed store
            const float4* src = (const float4*)(g_k + (size_t)(kt*64 + r)*NKVH*HD + kvh*HD + g*32);
            #pragma unroll
            for (int i4=0;i4<8;i4++) {
                float4 v = src[i4];
                int db = g*32 + i4*4;
                KV[(db+0)*QT_STRIDE + r] = v.x;
                KV[(db+1)*QT_STRIDE + r] = v.y;
                KV[(db+2)*QT_STRIDE + r] = v.z;
                KV[(db+3)*QT_STRIDE + r] = v.w;
            }
        }
        __syncthreads();
        { // S = Q K^T : rank-1 over d, contiguous float4 loads
            float acc[4][4];
            #pragma unroll
            for (int i=0;i<4;i++)
                #pragma unroll
                for (int j=0;j<4;j++) acc[i][j]=0.f;
            #pragma unroll 4
            for (int d=0; d<HD; d++) {
                float4 a4 = *(const float4*)&Qt[d*QT_STRIDE + 4*tr];
                float4 b4 = *(const float4*)&KV[d*QT_STRIDE + 4*tc];
                float a[4] = {a4.x,a4.y,a4.z,a4.w};
                float b[4] = {b4.x,b4.y,b4.z,b4.w};
                #pragma unroll
                for (int i=0;i<4;i++)
                    #pragma unroll
                    for (int j=0;j<4;j++) acc[i][j] += a[i]*b[j];
            }
            #pragma unroll
            for (int i=0;i<4;i++)
                #pragma unroll
                for (int j=0;j<4;j++) S[(4*tr+i)*S_STRIDE + 4*tc+j] = acc[i][j];
        }
        __syncthreads();
        { // online softmax update, then load V tile (row-major)
            float* Sr = S + r*S_STRIDE + g*16;
            float mloc = -1e30f;
            #pragma unroll
            for (int j=0;j<16;j++) mloc = fmaxf(mloc, Sr[j]);
            #pragma unroll
            for (int o=1;o<4;o<<=1) mloc = fmaxf(mloc, __shfl_xor_sync(0xffffffffu, mloc, o));
            float mold = mrow[r];
            float mnew = fmaxf(mold, mloc);
            float psum = 0.f;
            #pragma unroll
            for (int j=0;j<16;j++) { float pp = expf(Sr[j]-mnew); Sr[j]=pp; psum+=pp; }
            #pragma unroll
            for (int o=1;o<4;o<<=1) psum += __shfl_xor_sync(0xffffffffu, psum, o);
            if (g==0) {
                float alpha = expf(mold - mnew);
                arow[r] = alpha;
                mrow[r] = mnew;
                lrow[r] = lrow[r]*alpha + psum;
            }
            const float4* src = (const float4*)(g_v + (size_t)(kt*64 + r)*NKVH*HD + kvh*HD + g*32);
            float* dst = KV + r*V_STRIDE + g*32;
            #pragma unroll
            for (int i4=0;i4<8;i4++) *(float4*)(dst + i4*4) = src[i4];
        }
        __syncthreads();
        { // rescale O, accumulate P@V
            float al[4];
            #pragma unroll
            for (int i=0;i<4;i++) al[i] = arow[4*tr+i];
            #pragma unroll
            for (int i=0;i<4;i++)
                #pragma unroll
                for (int j=0;j<8;j++) O[i][j]*=al[i];
            for (int kk=0; kk<64; kk++) {
                float4 b0 = *(const float4*)&KV[kk*V_STRIDE + tc*8];
                float4 b1 = *(const float4*)&KV[kk*V_STRIDE + tc*8 + 4];
                float b[8] = {b0.x,b0.y,b0.z,b0.w,b1.x,b1.y,b1.z,b1.w};
                #pragma unroll
                for (int i=0;i<4;i++) {
                    float pv = S[(4*tr+i)*S_STRIDE + kk];
                    #pragma unroll
                    for (int j=0;j<8;j++) O[i][j] += pv*b[j];
                }
            }
        }
        __syncthreads();
    }
    #pragma unroll
    for (int i=0;i<4;i++) {
        int row = 4*tr+i;
        float linv = 1.0f / lrow[row];
        float* dst = g_ctx + (size_t)(qt*64+row)*HH + h*HD + tc*8;
        #pragma unroll
        for (int j=0;j<8;j++) dst[j] = O[i][j]*linv;
    }
}

// ---------------- router: logits, top-2, normalized weights ----------------
__global__ void router_kernel(const float* __restrict__ wr) {
    int t = blockIdx.x;
    float acc[NEXP];
    #pragma unroll
    for (int e=0;e<NEXP;e++) acc[e]=0.f;
    for (int j=threadIdx.x; j<HH; j+=256) {
        float x = g_h2[(size_t)t*HH+j];
        const float* w = wr + j*NEXP;
        #pragma unroll
        for (int e=0;e<NEXP;e++) acc[e] += x*w[e];
    }
    __shared__ float sred[256];
    __shared__ float logits[NEXP];
    for (int e=0;e<NEXP;e++) {
        sred[threadIdx.x]=acc[e]; __syncthreads();
        for (int s=128;s>0;s>>=1){ if(threadIdx.x<s) sred[threadIdx.x]+=sred[threadIdx.x+s]; __syncthreads(); }
        if (threadIdx.x==0) logits[e]=sred[0];
        __syncthreads();
    }
    if (threadIdx.x==0) {
        int i1=0; float l1=logits[0];
        for (int e=1;e<NEXP;e++) if (logits[e]>l1){l1=logits[e]; i1=e;}
        int i2=-1; float l2=-1e30f;
        for (int e=0;e<NEXP;e++) if (e!=i1 && logits[e]>l2){l2=logits[e]; i2=e;}
        float w1 = 1.0f/(1.0f+expf(l2-l1));
        g_topi[2*t]=i1; g_topi[2*t+1]=i2;
        g_topw[2*t]=w1; g_topw[2*t+1]=1.0f-w1;
    }
}

// ---------------- deterministic per-expert compaction (block scan) ----------------
__global__ void build_lists_kernel() {
    int e = blockIdx.x;
    int t = threadIdx.x; // 1024 threads
    int slot = -1;
    if (g_topi[2*t]==e) slot=0; else if (g_topi[2*t+1]==e) slot=1;
    int flag = (slot>=0) ? 1 : 0;
    unsigned mask = __ballot_sync(0xffffffffu, flag);
    int lane = t & 31, warp = t >> 5;
    int pos = __popc(mask & ((1u<<lane)-1u));
    __shared__ int wsum[32];
    if (lane==0) wsum[warp]=__popc(mask);
    __syncthreads();
    if (t < 32) {
        int v = wsum[t];
        #pragma unroll
        for (int o=1;o<32;o<<=1){ int n=__shfl_up_sync(0xffffffffu, v, o); if (t>=o) v+=n; }
        wsum[t]=v; // inclusive
    }
    __syncthreads();
    int base = (warp==0) ? 0 : wsum[warp-1];
    if (flag) g_list[e*TT + base + pos] = 2*t+slot;
    if (t==0) g_count[e]=wsum[31];
}

// ============ expert gate/up GEMM (gathered rows), K16 double-buffered ============
__global__ void __launch_bounds__(256) expert_gu_kernel(
        const float* __restrict__ W, float* __restrict__ out, int applySilu) {
    int e = blockIdx.z;
    int cnt = g_count[e];
    int by = blockIdx.y * 128;
    if (by >= cnt) return;
    int bx = blockIdx.x * 128;  // N = 768
    __shared__ float As[2][16][132];
    __shared__ float Bs[2][16][128];
    __shared__ int rows[128];
    int tid = threadIdx.x;
    if (tid < 128) {
        int idx = by + tid;
        rows[tid] = (idx < cnt) ? (g_list[e*TT + idx] >> 1) : 0;
    }
    __syncthreads();
    const float* Wb = W + (size_t)e * HH * II;
    int tx = tid & 15, ty = tid >> 4;
    int a_row = tid >> 1, a_h = (tid & 1) * 8;
    int b_kr = tid >> 4, b_c = (tid & 15) * 8;
    int a_grow = rows[a_row];
    float acc[8][8];
    #pragma unroll
    for (int i=0;i<8;i++)
        #pragma unroll
        for (int j=0;j<8;j++) acc[i][j]=0.f;

    float4 pa0, pa1, pb0, pb1;
    {
        const float4* ap = (const float4*)&g_h2[(size_t)a_grow*HH + a_h];
        pa0 = ap[0]; pa1 = ap[1];
        const float4* bp = (const float4*)&Wb[(size_t)b_kr*II + bx + b_c];
        pb0 = bp[0]; pb1 = bp[1];
        As[0][a_h+0][a_row]=pa0.x; As[0][a_h+1][a_row]=pa0.y;
        As[0][a_h+2][a_row]=pa0.z; As[0][a_h+3][a_row]=pa0.w;
        As[0][a_h+4][a_row]=pa1.x; As[0][a_h+5][a_row]=pa1.y;
        As[0][a_h+6][a_row]=pa1.z; As[0][a_h+7][a_row]=pa1.w;
        *(float4*)&Bs[0][b_kr][b_c]   = pb0;
        *(float4*)&Bs[0][b_kr][b_c+4] = pb1;
    }
    __syncthreads();
    const int ntiles = HH >> 4;
    for (int kt = 0; kt < ntiles; kt++) {
        int cur = kt & 1, nxt = cur ^ 1;
        if (kt+1 < ntiles) {
            int k0 = (kt+1) << 4;
            const float4* ap = (const float4*)&g_h2[(size_t)a_grow*HH + k0 + a_h];
            pa0 = ap[0]; pa1 = ap[1];
            const float4* bp = (const float4*)&Wb[(size_t)(k0+b_kr)*II + bx + b_c];
            pb0 = bp[0]; pb1 = bp[1];
        }
        #pragma unroll
        for (int kk = 0; kk < 16; kk++) {
            float4 a0 = *(const float4*)&As[cur][kk][ty*8];
            float4 a1 = *(const float4*)&As[cur][kk][ty*8+4];
            float4 b0 = *(const float4*)&Bs[cur][kk][tx*8];
            float4 b1 = *(const float4*)&Bs[cur][kk][tx*8+4];
            float a[8] = {a0.x,a0.y,a0.z,a0.w,a1.x,a1.y,a1.z,a1.w};
            float b[8] = {b0.x,b0.y,b0.z,b0.w,b1.x,b1.y,b1.z,b1.w};
            #pragma unroll
            for (int i=0;i<8;i++)
                #pragma unroll
                for (int j=0;j<8;j++) acc[i][j] += a[i]*b[j];
        }
        if (kt+1 < ntiles) {
            As[nxt][a_h+0][a_row]=pa0.x; As[nxt][a_h+1][a_row]=pa0.y;
            As[nxt][a_h+2][a_row]=pa0.z; As[nxt][a_h+3][a_row]=pa0.w;
            As[nxt][a_h+4][a_row]=pa1.x; As[nxt][a_h+5][a_row]=pa1.y;
            As[nxt][a_h+6][a_row]=pa1.z; As[nxt][a_h+7][a_row]=pa1.w;
            *(float4*)&Bs[nxt][b_kr][b_c]   = pb0;
            *(float4*)&Bs[nxt][b_kr][b_c+4] = pb1;
        }
        __syncthreads();
    }
    #pragma unroll
    for (int i=0;i<8;i++) {
        int m = by + ty*8 + i;
        if (m < cnt) {
            float* dst = out + ((size_t)e*TT + m)*II + bx + tx*8;
            #pragma unroll
            for (int j=0;j<8;j++) {
                float v = acc[i][j];
                if (applySilu) v = v / (1.0f + expf(-v));
                dst[j] = v;
            }
        }
    }
}

// ============ expert down GEMM: (silu(g)*u) @ Wd -> yslot, K16 double-buffered ============
__global__ void __launch_bounds__(256) expert_down_kernel(const float* __restrict__ Wd) {
    int e = blockIdx.z;
    int cnt = g_count[e];
    int by = blockIdx.y * 128;
    if (by >= cnt) return;
    int bx = blockIdx.x * 128;  // N = 2048
    __shared__ float As[2][16][132];
    __shared__ float Bs[2][16][128];
    int tid = threadIdx.x;
    int tx = tid & 15, ty = tid >> 4;
    int a_row = tid >> 1, a_h = (tid & 1) * 8;
    int b_kr = tid >> 4, b_c = (tid & 15) * 8;
    float acc[8][8];
    #pragma unroll
    for (int i=0;i<8;i++)
        #pragma unroll
        for (int j=0;j<8;j++) acc[i][j]=0.f;
    const float* Wb = Wd + (size_t)e*II*HH;
    size_t abase = ((size_t)e*TT + by + a_row)*II;
    float4 pa0, pa1, pb0, pb1;
    {
        const float4* gp = (const float4*)&g_gbuf[abase + a_h];
        const float4* up = (const float4*)&g_ubuf[abase + a_h];
        float4 gg0=gp[0], gg1=gp[1], uu0=up[0], uu1=up[1];
        pa0 = make_float4(gg0.x*uu0.x, gg0.y*uu0.y, gg0.z*uu0.z, gg0.w*uu0.w);
        pa1 = make_float4(gg1.x*uu1.x, gg1.y*uu1.y, gg1.z*uu1.z, gg1.w*uu1.w);
        const float4* bp = (const float4*)&Wb[(size_t)b_kr*HH + bx + b_c];
        pb0 = bp[0]; pb1 = bp[1];
        As[0][a_h+0][a_row]=pa0.x; As[0][a_h+1][a_row]=pa0.y;
        As[0][a_h+2][a_row]=pa0.z; As[0][a_h+3][a_row]=pa0.w;
        As[0][a_h+4][a_row]=pa1.x; As[0][a_h+5][a_row]=pa1.y;
        As[0][a_h+6][a_row]=pa1.z; As[0][a_h+7][a_row]=pa1.w;
        *(float4*)&Bs[0][b_kr][b_c]   = pb0;
        *(float4*)&Bs[0][b_kr][b_c+4] = pb1;
    }
    __syncthreads();
    const int ntiles = II >> 4;
    for (int kt = 0; kt < ntiles; kt++) {
        int cur = kt & 1, nxt = cur ^ 1;
        if (kt+1 < ntiles) {
            int k0 = (kt+1) << 4;
            const float4* gp = (const float4*)&g_gbuf[abase + k0 + a_h];
            const float4* up = (const float4*)&g_ubuf[abase + k0 + a_h];
            float4 gg0=gp[0], gg1=gp[1], uu0=up[0], uu1=up[1];
            pa0 = make_float4(gg0.x*uu0.x, gg0.y*uu0.y, gg0.z*uu0.z, gg0.w*uu0.w);
            pa1 = make_float4(gg1.x*uu1.x, gg1.y*uu1.y, gg1.z*uu1.z, gg1.w*uu1.w);
            const float4* bp = (const float4*)&Wb[(size_t)(k0+b_kr)*HH + bx + b_c];
            pb0 = bp[0]; pb1 = bp[1];
        }
        #pragma unroll
        for (int kk = 0; kk < 16; kk++) {
            float4 a0 = *(const float4*)&As[cur][kk][ty*8];
            float4 a1 = *(const float4*)&As[cur][kk][ty*8+4];
            float4 b0 = *(const float4*)&Bs[cur][kk][tx*8];
            float4 b1 = *(const float4*)&Bs[cur][kk][tx*8+4];
            float a[8] = {a0.x,a0.y,a0.z,a0.w,a1.x,a1.y,a1.z,a1.w};
            float b[8] = {b0.x,b0.y,b0.z,b0.w,b1.x,b1.y,b1.z,b1.w};
            #pragma unroll
            for (int i=0;i<8;i++)
                #pragma unroll
                for (int j=0;j<8;j++) acc[i][j] += a[i]*b[j];
        }
        if (kt+1 < ntiles) {
            As[nxt][a_h+0][a_row]=pa0.x; As[nxt][a_h+1][a_row]=pa0.y;
            As[nxt][a_h+2][a_row]=pa0.z; As[nxt][a_h+3][a_row]=pa0.w;
            As[nxt][a_h+4][a_row]=pa1.x; As[nxt][a_h+5][a_row]=pa1.y;
            As[nxt][a_h+6][a_row]=pa1.z; As[nxt][a_h+7][a_row]=pa1.w;
            *(float4*)&Bs[nxt][b_kr][b_c]   = pb0;
            *(float4*)&Bs[nxt][b_kr][b_c+4] = pb1;
        }
        __syncthreads();
    }
    #pragma unroll
    for (int i=0;i<8;i++) {
        int m = by + ty*8 + i;
        if (m < cnt) {
            int entry = g_list[e*TT + m];
            float* dst = g_yslot + (size_t)entry*HH + bx + tx*8;
            float4 v0 = make_float4(acc[i][0],acc[i][1],acc[i][2],acc[i][3]);
            float4 v1 = make_float4(acc[i][4],acc[i][5],acc[i][6],acc[i][7]);
            *(float4*)dst = v0;
            *(float4*)(dst+4) = v1;
        }
    }
}

// ---------------- final combine ----------------
__global__ void combine_kernel(float* __restrict__ out) {
    int t = blockIdx.x;
    float w0 = g_topw[2*t], w1 = g_topw[2*t+1];
    const float* y0 = g_yslot + (size_t)(2*t)*HH;
    const float* y1 = y0 + HH;
    float* o = out + (size_t)t*HH;
    for (int j=threadIdx.x;j<HH;j+=256) o[j] = w0*y0[j] + w1*y1[j];
}

// ---------------- launch ----------------
extern "C" void kernel_launch(void* const* d_in, const int* in_sizes, int n_in,
                              void* d_out, int out_size) {
    const float* hidden   = (const float*)d_in[0];
    const int*   pos      = (const int*)  d_in[1];
    const float* w_norm1  = (const float*)d_in[2];
    const float* w_norm2  = (const float*)d_in[3];
    const float* w_qkv    = (const float*)d_in[4];
    const float* w_qnorm  = (const float*)d_in[5];
    const float* w_knorm  = (const float*)d_in[6];
    const float* w_o      = (const float*)d_in[7];
    const float* w_router = (const float*)d_in[8];
    const float* w_gate   = (const float*)d_in[9];
    const float* w_up     = (const float*)d_in[10];
    const float* w_down   = (const float*)d_in[11];
    (void)in_sizes; (void)n_in; (void)out_size;

    float* moe_out = (float*)d_out;
    float* resid   = (float*)d_out + (size_t)TT*HH;

    void* p;
    cudaGetSymbolAddress(&p, g_h1);   float* h1   = (float*)p;
    cudaGetSymbolAddress(&p, g_qkv);  float* qkv  = (float*)p;
    cudaGetSymbolAddress(&p, g_ctx);  float* ctx  = (float*)p;
    cudaGetSymbolAddress(&p, g_h2);   float* h2   = (float*)p;
    cudaGetSymbolAddress(&p, g_gbuf); float* gbuf = (float*)p;
    cudaGetSymbolAddress(&p, g_ubuf); float* ubuf = (float*)p;

    int attn_smem = (128*QT_STRIDE*2 + 64*S_STRIDE + 192) * 4;
    cudaFuncSetAttribute(attn_kernel, cudaFuncAttributeMaxDynamicSharedMemorySize, attn_smem);

    rmsnorm_kernel<<<TT, 256>>>(hidden, w_norm1, h1);
    sgemm16_kernel<<<dim3(QKVN/128, TT/128), 256>>>(h1, w_qkv, qkv, TT, QKVN, HH, nullptr);
    qkv_post_kernel<<<dim3(24, TT), 128>>>(pos, w_qnorm, w_knorm);
    attn_kernel<<<dim3(NHEAD, TT/64), 256, attn_smem>>>();
    sgemm16_kernel<<<dim3(HH/128, TT/128), 256>>>(ctx, w_o, resid, TT, HH, HH, hidden);
    rmsnorm_kernel<<<TT, 256>>>(resid, w_norm2, h2);
    router_kernel<<<TT, 256>>>(w_router);
    build_lists_kernel<<<NEXP, TT>>>();
    expert_gu_kernel<<<dim3(II/128, TT/128, NEXP), 256>>>(w_gate, gbuf, 1);
    expert_gu_kernel<<<dim3(II/128, TT/128, NEXP), 256>>>(w_up, ubuf, 0);
    expert_down_kernel<<<dim3(HH/128, TT/128, NEXP), 256>>>(w_down);
    combine_kernel<<<TT, 256>>>(moe_out);
}

// round 16
// speedup vs baseline: 2.3175x; 1.5177x over previous
#include <cuda_runtime.h>
#include <cuda_bf16.h>
#include <mma.h>
#include <math.h>

using namespace nvcuda;

// ---------------- problem constants ----------------
#define TT 1024
#define HH 2048
#define NHEAD 16
#define NKVH 4
#define HD 128
#define NEXP 16
#define II 768
#define QKVN 3072
#define EPSV 1e-6f

// ---------------- device scratch ----------------
__device__ float g_h1[TT*HH];
__device__ float g_qkv[TT*QKVN];
__device__ float g_q[TT*NHEAD*HD];
__device__ float g_k[TT*NKVH*HD];
__device__ float g_v[TT*NKVH*HD];
__device__ float g_ctx[TT*HH];
__device__ float g_h2[TT*HH];
__device__ int   g_topi[TT*2];
__device__ float g_topw[TT*2];
__device__ int   g_list[NEXP*TT];
__device__ int   g_count[NEXP];
__device__ float g_gbuf[NEXP*TT*II];
__device__ float g_ubuf[NEXP*TT*II];
__device__ float g_yslot[TT*2*HH];

__device__ __forceinline__ void split_bf16(float v, __nv_bfloat16& hi, __nv_bfloat16& lo){
    hi = __float2bfloat16_rn(v);
    lo = __float2bfloat16_rn(v - __bfloat162float(hi));
}

// ================= WMMA bf16 split GEMM: 128x128 tile =================
// mode 0: C[M,N] = A[M,K] @ B[K,N] (+addend)
// mode 1: gathered rows of g_h2 @ B[e] -> C[e*TT+m]  (silu opt)
// mode 2: (g_gbuf*g_ubuf)[e rows] @ B[e] -> scatter g_yslot
#define KC 32
#define A_LD 40
#define B_LD 136
#define ST_LD 132
// tiles: Ahi 0..10240, Alo 10240..20480, Bhi 20480..29184, Blo 29184..37888
// staging (after mainloop): fp32 128*132*4 = 67584
#define WG_SMEM 67584

__global__ void __launch_bounds__(256) wg_gemm_kernel(
    const float* __restrict__ A, const float* __restrict__ Bsrc, float* __restrict__ Cdst,
    int N, int K, const float* __restrict__ addend, int mode, int applySilu)
{
    int e  = blockIdx.z;
    int by = blockIdx.y * 128;
    int bx = blockIdx.x * 128;
    int cnt = TT;
    if (mode >= 1) { cnt = g_count[e]; if (by >= cnt) return; }

    extern __shared__ char smc[];
    __nv_bfloat16* Ahi = (__nv_bfloat16*)(smc);
    __nv_bfloat16* Alo = (__nv_bfloat16*)(smc + 10240);
    __nv_bfloat16* Bhi = (__nv_bfloat16*)(smc + 20480);
    __nv_bfloat16* Blo = (__nv_bfloat16*)(smc + 29184);
    float* stage = (float*)smc;

    int tid = threadIdx.x, wid = tid >> 5;
    __shared__ int rows_s[128];
    if (mode==1 && tid<128) {
        int idx = by + tid;
        rows_s[tid] = (idx < cnt) ? (g_list[e*TT+idx] >> 1) : (g_list[e*TT] >> 1);
    }
    __syncthreads();

    const float* Bp = Bsrc + (mode>=1 ? (size_t)e*(size_t)K*(size_t)N : 0);
    int a_row = tid >> 1, a_h = (tid & 1) * 16;   // A: row, 16 k's
    int b_kr = tid >> 3, b_c = (tid & 7) * 16;    // B: k-row 0..31, 16 n's
    int wm = wid & 3, wn = wid >> 2;              // warp: M strip (32), N strip (64)

    wmma::fragment<wmma::accumulator,16,16,16,float> acc[2][4];
    #pragma unroll
    for (int i=0;i<2;i++)
        #pragma unroll
        for (int j=0;j<4;j++) wmma::fill_fragment(acc[i][j], 0.f);

    for (int k0 = 0; k0 < K; k0 += KC) {
        // ---- A tile: 128 x 32 fp32 -> hi/lo bf16 [m][k] ----
        #pragma unroll
        for (int ii=0; ii<4; ii++) {
            int kk = a_h + 4*ii;
            float4 v;
            if (mode==0) {
                v = *(const float4*)(A + (size_t)(by+a_row)*K + k0 + kk);
            } else if (mode==1) {
                v = *(const float4*)(g_h2 + (size_t)rows_s[a_row]*HH + k0 + kk);
            } else {
                size_t base = ((size_t)e*TT + by + a_row)*II + k0 + kk;
                float4 g4 = *(const float4*)(g_gbuf + base);
                float4 u4 = *(const float4*)(g_ubuf + base);
                v = make_float4(g4.x*u4.x, g4.y*u4.y, g4.z*u4.z, g4.w*u4.w);
            }
            __nv_bfloat16 h0,h1,h2,h3,l0,l1,l2,l3;
            split_bf16(v.x,h0,l0); split_bf16(v.y,h1,l1);
            split_bf16(v.z,h2,l2); split_bf16(v.w,h3,l3);
            int idx = a_row*A_LD + kk;
            __nv_bfloat162* ph = (__nv_bfloat162*)&Ahi[idx];
            __nv_bfloat162* pl = (__nv_bfloat162*)&Alo[idx];
            ph[0] = __nv_bfloat162(h0,h1); ph[1] = __nv_bfloat162(h2,h3);
            pl[0] = __nv_bfloat162(l0,l1); pl[1] = __nv_bfloat162(l2,l3);
        }
        // ---- B tile: 32 x 128 fp32 -> hi/lo bf16 [k][n] ----
        #pragma unroll
        for (int ii=0; ii<4; ii++) {
            int nn = b_c + 4*ii;
            float4 v = *(const float4*)(Bp + (size_t)(k0+b_kr)*N + bx + nn);
            __nv_bfloat16 h0,h1,h2,h3,l0,l1,l2,l3;
            split_bf16(v.x,h0,l0); split_bf16(v.y,h1,l1);
            split_bf16(v.z,h2,l2); split_bf16(v.w,h3,l3);
            int idx = b_kr*B_LD + nn;
            __nv_bfloat162* ph = (__nv_bfloat162*)&Bhi[idx];
            __nv_bfloat162* pl = (__nv_bfloat162*)&Blo[idx];
            ph[0] = __nv_bfloat162(h0,h1); ph[1] = __nv_bfloat162(h2,h3);
            pl[0] = __nv_bfloat162(l0,l1); pl[1] = __nv_bfloat162(l2,l3);
        }
        __syncthreads();
        #pragma unroll
        for (int kk=0; kk<2; kk++) {
            wmma::fragment<wmma::matrix_a,16,16,16,__nv_bfloat16,wmma::row_major> ah[2], al[2];
            wmma::fragment<wmma::matrix_b,16,16,16,__nv_bfloat16,wmma::row_major> bh[4], bl[4];
            #pragma unroll
            for (int i=0;i<2;i++) {
                wmma::load_matrix_sync(ah[i], &Ahi[(wm*32 + i*16)*A_LD + kk*16], A_LD);
                wmma::load_matrix_sync(al[i], &Alo[(wm*32 + i*16)*A_LD + kk*16], A_LD);
            }
            #pragma unroll
            for (int j=0;j<4;j++) {
                wmma::load_matrix_sync(bh[j], &Bhi[(kk*16)*B_LD + wn*64 + j*16], B_LD);
                wmma::load_matrix_sync(bl[j], &Blo[(kk*16)*B_LD + wn*64 + j*16], B_LD);
            }
            #pragma unroll
            for (int i=0;i<2;i++)
                #pragma unroll
                for (int j=0;j<4;j++) {
                    wmma::mma_sync(acc[i][j], ah[i], bh[j], acc[i][j]);
                    wmma::mma_sync(acc[i][j], ah[i], bl[j], acc[i][j]);
                    wmma::mma_sync(acc[i][j], al[i], bh[j], acc[i][j]);
                }
        }
        __syncthreads();
    }
    // ---- store accumulators to fp32 staging (overlays tiles; safe after sync) ----
    #pragma unroll
    for (int i=0;i<2;i++)
        #pragma unroll
        for (int j=0;j<4;j++)
            wmma::store_matrix_sync(&stage[(wm*32 + i*16)*ST_LD + wn*64 + j*16],
                                    acc[i][j], ST_LD, wmma::mem_row_major);
    __syncthreads();
    // ---- guarded copy-out ----
    {
        int m_loc = tid >> 1, half = tid & 1;
        int m = by + m_loc;
        if (m < cnt) {
            const float* srow = stage + m_loc*ST_LD + half*64;
            float* dst;
            const float* ad = nullptr;
            int ng0 = bx + half*64;
            if (mode==0) {
                dst = Cdst + (size_t)m*N + ng0;
                if (addend) ad = addend + (size_t)m*N + ng0;
            } else if (mode==1) {
                dst = Cdst + ((size_t)e*TT + m)*N + ng0;
            } else {
                int entry = g_list[e*TT + m];
                dst = g_yslot + (size_t)entry*HH + ng0;
            }
            #pragma unroll
            for (int c4=0; c4<64; c4+=4) {
                float x0 = srow[c4+0], x1 = srow[c4+1], x2 = srow[c4+2], x3 = srow[c4+3];
                if (applySilu) {
                    x0 = x0/(1.f+expf(-x0)); x1 = x1/(1.f+expf(-x1));
                    x2 = x2/(1.f+expf(-x2)); x3 = x3/(1.f+expf(-x3));
                }
                if (ad) {
                    float4 a4 = *(const float4*)(ad + c4);
                    x0+=a4.x; x1+=a4.y; x2+=a4.z; x3+=a4.w;
                }
                *(float4*)(dst + c4) = make_float4(x0,x1,x2,x3);
            }
        }
    }
}

// ---------------- rmsnorm over 2048 ----------------
__global__ void rmsnorm_kernel(const float* __restrict__ x, const float* __restrict__ w,
                               float* __restrict__ out) {
    int t = blockIdx.x;
    const float* row = x + (size_t)t*HH;
    float ss = 0.f;
    for (int j = threadIdx.x; j < HH; j += 256) { float v = row[j]; ss += v*v; }
    __shared__ float sred[256];
    sred[threadIdx.x] = ss; __syncthreads();
    for (int s = 128; s > 0; s >>= 1) {
        if (threadIdx.x < s) sred[threadIdx.x] += sred[threadIdx.x+s];
        __syncthreads();
    }
    float scale = rsqrtf(sred[0]/(float)HH + EPSV);
    for (int j = threadIdx.x; j < HH; j += 256)
        out[(size_t)t*HH + j] = row[j]*scale*w[j];
}

// ---------------- per-(token,head) qk rmsnorm + rope; v copy ----------------
__global__ void qkv_post_kernel(const int* __restrict__ pos,
                                const float* __restrict__ wq, const float* __restrict__ wk) {
    int t = blockIdx.y;
    int slot = blockIdx.x;
    int d = threadIdx.x;
    const float* src;
    if (slot < 16)       src = g_qkv + (size_t)t*QKVN + slot*HD;
    else if (slot < 20)  src = g_qkv + (size_t)t*QKVN + 2048 + (slot-16)*HD;
    else                 src = g_qkv + (size_t)t*QKVN + 2560 + (slot-20)*HD;
    float v = src[d];
    if (slot >= 20) { g_v[(size_t)t*NKVH*HD + (slot-20)*HD + d] = v; return; }
    float x2 = v*v;
    #pragma unroll
    for (int o=16;o;o>>=1) x2 += __shfl_xor_sync(0xffffffffu, x2, o);
    __shared__ float wsum[4];
    if ((d&31)==0) wsum[d>>5] = x2;
    __syncthreads();
    float tot = wsum[0]+wsum[1]+wsum[2]+wsum[3];
    float scale = rsqrtf(tot/(float)HD + EPSV);
    const float* wn = (slot<16)? wq : wk;
    float xn = v * scale * wn[d];
    __shared__ float sh[128];
    sh[d] = xn; __syncthreads();
    int i = d & 63;
    float inv = expf(-(float)i * (logf(10000.0f)/64.0f));
    float ang = (float)pos[t] * inv;
    float c = cosf(ang), s = sinf(ang);
    float o;
    if (d < 64) o = sh[d]*c - sh[d+64]*s;
    else        o = sh[d]*c + sh[d-64]*s;
    if (slot < 16) g_q[(size_t)t*NHEAD*HD + slot*HD + d] = o * 0.08838834764831845f;
    else           g_k[(size_t)t*NKVH*HD + (slot-16)*HD + d] = o;
}

// ---------------- flash-style attention (R8 winner, unchanged) ----------------
#define QT_STRIDE 68
#define V_STRIDE  132
#define S_STRIDE  66
__global__ void __launch_bounds__(256) attn_kernel() {
    extern __shared__ float sm[];
    float* Qt   = sm;
    float* KV   = sm + 128*QT_STRIDE;
    float* S    = KV + 128*QT_STRIDE;
    float* mrow = S + 64*S_STRIDE;
    float* lrow = mrow + 64;
    float* arow = lrow + 64;
    int h = blockIdx.x, qt = blockIdx.y;
    int kvh = h >> 2;
    int tid = threadIdx.x;
    int r = tid >> 2, g = tid & 3;
    int tr = tid >> 4, tc = tid & 15;
    {
        const float4* src = (const float4*)(g_q + (size_t)(qt*64 + r)*HH + h*HD + g*32);
        #pragma unroll
        for (int i4=0;i4<8;i4++) {
            float4 v = src[i4];
            int db = g*32 + i4*4;
            Qt[(db+0)*QT_STRIDE + r] = v.x;
            Qt[(db+1)*QT_STRIDE + r] = v.y;
            Qt[(db+2)*QT_STRIDE + r] = v.z;
            Qt[(db+3)*QT_STRIDE + r] = v.w;
        }
    }
    if (tid < 64) { mrow[tid] = -1e30f; lrow[tid] = 0.f; }
    float O[4][8];
    #pragma unroll
    for (int i=0;i<4;i++)
        #pragma unroll
        for (int j=0;j<8;j++) O[i][j]=0.f;
    __syncthreads();
    for (int kt = 0; kt < 16; kt++) {
        {
            const float4* src = (const float4*)(g_k + (size_t)(kt*64 + r)*NKVH*HD + kvh*HD + g*32);
            #pragma unroll
            for (int i4=0;i4<8;i4++) {
                float4 v = src[i4];
                int db = g*32 + i4*4;
                KV[(db+0)*QT_STRIDE + r] = v.x;
                KV[(db+1)*QT_STRIDE + r] = v.y;
                KV[(db+2)*QT_STRIDE + r] = v.z;
                KV[(db+3)*QT_STRIDE + r] = v.w;
            }
        }
        __syncthreads();
        {
            float acc[4][4];
            #pragma unroll
            for (int i=0;i<4;i++)
                #pragma unroll
                for (int j=0;j<4;j++) acc[i][j]=0.f;
            #pragma unroll 4
            for (int d=0; d<HD; d++) {
                float4 a4 = *(const float4*)&Qt[d*QT_STRIDE + 4*tr];
                float4 b4 = *(const float4*)&KV[d*QT_STRIDE + 4*tc];
                float a[4] = {a4.x,a4.y,a4.z,a4.w};
                float b[4] = {b4.x,b4.y,b4.z,b4.w};
                #pragma unroll
                for (int i=0;i<4;i++)
                    #pragma unroll
                    for (int j=0;j<4;j++) acc[i][j] += a[i]*b[j];
            }
            #pragma unroll
            for (int i=0;i<4;i++)
                #pragma unroll
                for (int j=0;j<4;j++) S[(4*tr+i)*S_STRIDE + 4*tc+j] = acc[i][j];
        }
        __syncthreads();
        {
            float* Sr = S + r*S_STRIDE + g*16;
            float mloc = -1e30f;
            #pragma unroll
            for (int j=0;j<16;j++) mloc = fmaxf(mloc, Sr[j]);
            #pragma unroll
            for (int o=1;o<4;o<<=1) mloc = fmaxf(mloc, __shfl_xor_sync(0xffffffffu, mloc, o));
            float mold = mrow[r];
            float mnew = fmaxf(mold, mloc);
            float psum = 0.f;
            #pragma unroll
            for (int j=0;j<16;j++) { float pp = expf(Sr[j]-mnew); Sr[j]=pp; psum+=pp; }
            #pragma unroll
            for (int o=1;o<4;o<<=1) psum += __shfl_xor_sync(0xffffffffu, psum, o);
            if (g==0) {
                float alpha = expf(mold - mnew);
                arow[r] = alpha;
                mrow[r] = mnew;
                lrow[r] = lrow[r]*alpha + psum;
            }
            const float4* src = (const float4*)(g_v + (size_t)(kt*64 + r)*NKVH*HD + kvh*HD + g*32);
            float* dst = KV + r*V_STRIDE + g*32;
            #pragma unroll
            for (int i4=0;i4<8;i4++) *(float4*)(dst + i4*4) = src[i4];
        }
        __syncthreads();
        {
            float al[4];
            #pragma unroll
            for (int i=0;i<4;i++) al[i] = arow[4*tr+i];
            #pragma unroll
            for (int i=0;i<4;i++)
                #pragma unroll
                for (int j=0;j<8;j++) O[i][j]*=al[i];
            for (int kk=0; kk<64; kk++) {
                float4 b0 = *(const float4*)&KV[kk*V_STRIDE + tc*8];
                float4 b1 = *(const float4*)&KV[kk*V_STRIDE + tc*8 + 4];
                float b[8] = {b0.x,b0.y,b0.z,b0.w,b1.x,b1.y,b1.z,b1.w};
                #pragma unroll
                for (int i=0;i<4;i++) {
                    float pv = S[(4*tr+i)*S_STRIDE + kk];
                    #pragma unroll
                    for (int j=0;j<8;j++) O[i][j] += pv*b[j];
                }
            }
        }
        __syncthreads();
    }
    #pragma unroll
    for (int i=0;i<4;i++) {
        int row = 4*tr+i;
        float linv = 1.0f / lrow[row];
        float* dst = g_ctx + (size_t)(qt*64+row)*HH + h*HD + tc*8;
        #pragma unroll
        for (int j=0;j<8;j++) dst[j] = O[i][j]*linv;
    }
}

// ---------------- router ----------------
__global__ void router_kernel(const float* __restrict__ wr) {
    int t = blockIdx.x;
    float acc[NEXP];
    #pragma unroll
    for (int e=0;e<NEXP;e++) acc[e]=0.f;
    for (int j=threadIdx.x; j<HH; j+=256) {
        float x = g_h2[(size_t)t*HH+j];
        const float* w = wr + j*NEXP;
        #pragma unroll
        for (int e=0;e<NEXP;e++) acc[e] += x*w[e];
    }
    __shared__ float sred[256];
    __shared__ float logits[NEXP];
    for (int e=0;e<NEXP;e++) {
        sred[threadIdx.x]=acc[e]; __syncthreads();
        for (int s=128;s>0;s>>=1){ if(threadIdx.x<s) sred[threadIdx.x]+=sred[threadIdx.x+s]; __syncthreads(); }
        if (threadIdx.x==0) logits[e]=sred[0];
        __syncthreads();
    }
    if (threadIdx.x==0) {
        int i1=0; float l1=logits[0];
        for (int e=1;e<NEXP;e++) if (logits[e]>l1){l1=logits[e]; i1=e;}
        int i2=-1; float l2=-1e30f;
        for (int e=0;e<NEXP;e++) if (e!=i1 && logits[e]>l2){l2=logits[e]; i2=e;}
        float w1 = 1.0f/(1.0f+expf(l2-l1));
        g_topi[2*t]=i1; g_topi[2*t+1]=i2;
        g_topw[2*t]=w1; g_topw[2*t+1]=1.0f-w1;
    }
}

// ---------------- deterministic per-expert compaction ----------------
__global__ void build_lists_kernel() {
    int e = blockIdx.x;
    int t = threadIdx.x;
    int slot = -1;
    if (g_topi[2*t]==e) slot=0; else if (g_topi[2*t+1]==e) slot=1;
    int flag = (slot>=0) ? 1 : 0;
    unsigned mask = __ballot_sync(0xffffffffu, flag);
    int lane = t & 31, warp = t >> 5;
    int pos = __popc(mask & ((1u<<lane)-1u));
    __shared__ int wsum[32];
    if (lane==0) wsum[warp]=__popc(mask);
    __syncthreads();
    if (t < 32) {
        int v = wsum[t];
        #pragma unroll
        for (int o=1;o<32;o<<=1){ int n=__shfl_up_sync(0xffffffffu, v, o); if (t>=o) v+=n; }
        wsum[t]=v;
    }
    __syncthreads();
    int base = (warp==0) ? 0 : wsum[warp-1];
    if (flag) g_list[e*TT + base + pos] = 2*t+slot;
    if (t==0) g_count[e]=wsum[31];
}

// ---------------- final combine ----------------
__global__ void combine_kernel(float* __restrict__ out) {
    int t = blockIdx.x;
    float w0 = g_topw[2*t], w1 = g_topw[2*t+1];
    const float* y0 = g_yslot + (size_t)(2*t)*HH;
    const float* y1 = y0 + HH;
    float* o = out + (size_t)t*HH;
    for (int j=threadIdx.x;j<HH;j+=256) o[j] = w0*y0[j] + w1*y1[j];
}

// ---------------- launch ----------------
extern "C" void kernel_launch(void* const* d_in, const int* in_sizes, int n_in,
                              void* d_out, int out_size) {
    const float* hidden   = (const float*)d_in[0];
    const int*   pos      = (const int*)  d_in[1];
    const float* w_norm1  = (const float*)d_in[2];
    const float* w_norm2  = (const float*)d_in[3];
    const float* w_qkv    = (const float*)d_in[4];
    const float* w_qnorm  = (const float*)d_in[5];
    const float* w_knorm  = (const float*)d_in[6];
    const float* w_o      = (const float*)d_in[7];
    const float* w_router = (const float*)d_in[8];
    const float* w_gate   = (const float*)d_in[9];
    const float* w_up     = (const float*)d_in[10];
    const float* w_down   = (const float*)d_in[11];
    (void)in_sizes; (void)n_in; (void)out_size;

    float* moe_out = (float*)d_out;
    float* resid   = (float*)d_out + (size_t)TT*HH;

    void* p;
    cudaGetSymbolAddress(&p, g_h1);   float* h1   = (float*)p;
    cudaGetSymbolAddress(&p, g_qkv);  float* qkv  = (float*)p;
    cudaGetSymbolAddress(&p, g_ctx);  float* ctx  = (float*)p;
    cudaGetSymbolAddress(&p, g_h2);   float* h2   = (float*)p;
    cudaGetSymbolAddress(&p, g_gbuf); float* gbuf = (float*)p;
    cudaGetSymbolAddress(&p, g_ubuf); float* ubuf = (float*)p;

    int attn_smem = (128*QT_STRIDE*2 + 64*S_STRIDE + 192) * 4;
    cudaFuncSetAttribute(attn_kernel, cudaFuncAttributeMaxDynamicSharedMemorySize, attn_smem);
    cudaFuncSetAttribute(wg_gemm_kernel, cudaFuncAttributeMaxDynamicSharedMemorySize, WG_SMEM);

    rmsnorm_kernel<<<TT, 256>>>(hidden, w_norm1, h1);
    wg_gemm_kernel<<<dim3(QKVN/128, TT/128, 1), 256, WG_SMEM>>>(h1, w_qkv, qkv, QKVN, HH, nullptr, 0, 0);
    qkv_post_kernel<<<dim3(24, TT), 128>>>(pos, w_qnorm, w_knorm);
    attn_kernel<<<dim3(NHEAD, TT/64), 256, attn_smem>>>();
    wg_gemm_kernel<<<dim3(HH/128, TT/128, 1), 256, WG_SMEM>>>(ctx, w_o, resid, HH, HH, hidden, 0, 0);
    rmsnorm_kernel<<<TT, 256>>>(resid, w_norm2, h2);
    router_kernel<<<TT, 256>>>(w_router);
    build_lists_kernel<<<NEXP, TT>>>();
    wg_gemm_kernel<<<dim3(II/128, TT/128, NEXP), 256, WG_SMEM>>>(nullptr, w_gate, gbuf, II, HH, nullptr, 1, 1);
    wg_gemm_kernel<<<dim3(II/128, TT/128, NEXP), 256, WG_SMEM>>>(nullptr, w_up,   ubuf, II, HH, nullptr, 1, 0);
    wg_gemm_kernel<<<dim3(HH/128, TT/128, NEXP), 256, WG_SMEM>>>(nullptr, w_down, nullptr, HH, II, nullptr, 2, 0);
    combine_kernel<<<TT, 256>>>(moe_out);
}

// round 17
// speedup vs baseline: 2.5357x; 1.0941x over previous
#include <cuda_runtime.h>
#include <cuda_bf16.h>
#include <mma.h>
#include <math.h>

using namespace nvcuda;

// ---------------- problem constants ----------------
#define TT 1024
#define HH 2048
#define NHEAD 16
#define NKVH 4
#define HD 128
#define NEXP 16
#define II 768
#define QKVN 3072
#define EPSV 1e-6f

// ---------------- device scratch ----------------
__device__ float g_h1[TT*HH];
__device__ float g_qkv[TT*QKVN];
__device__ float g_q[TT*NHEAD*HD];
__device__ float g_k[TT*NKVH*HD];
__device__ float g_v[TT*NKVH*HD];
__device__ float g_ctx[TT*HH];
__device__ float g_h2[TT*HH];
__device__ int   g_topi[TT*2];
__device__ float g_topw[TT*2];
__device__ int   g_list[NEXP*TT];
__device__ int   g_count[NEXP];
__device__ float g_gbuf[NEXP*TT*II];
__device__ float g_ubuf[NEXP*TT*II];
__device__ float g_yslot[TT*2*HH];

__device__ __forceinline__ void split_bf16(float v, __nv_bfloat16& hi, __nv_bfloat16& lo){
    hi = __float2bfloat16_rn(v);
    lo = __float2bfloat16_rn(v - __bfloat162float(hi));
}

// ================= WMMA bf16 split GEMM: 128x128 tile, double-buffered =================
// mode 0: C[M,N] = A[M,K] @ B[K,N] (+addend)
// mode 1: gathered rows of g_h2 @ B[e] -> C[e*TT+m]  (silu opt)
// mode 2: (g_gbuf*g_ubuf)[e rows] @ B[e] -> scatter g_yslot
#define KC 32
#define A_LD 40
#define B_LD 136
#define ST_LD 132
// per-buffer: Ahi 10240 + Alo 10240 + Bhi 8704 + Blo 8704 = 37888; x2 = 75776
// staging fp32 128*132*4 = 67584 overlays after mainloop
#define BUF_SZ 37888
#define WG_SMEM 75776

__global__ void __launch_bounds__(256) wg_gemm_kernel(
    const float* __restrict__ A, const float* __restrict__ Bsrc, float* __restrict__ Cdst,
    int N, int K, const float* __restrict__ addend, int mode, int applySilu)
{
    int e  = blockIdx.z;
    int by = blockIdx.y * 128;
    int bx = blockIdx.x * 128;
    int cnt = TT;
    if (mode >= 1) { cnt = g_count[e]; if (by >= cnt) return; }

    extern __shared__ char smc[];
    float* stage = (float*)smc;

    int tid = threadIdx.x, wid = tid >> 5;
    __shared__ int rows_s[128];
    if (mode==1 && tid<128) {
        int idx = by + tid;
        rows_s[tid] = (idx < cnt) ? (g_list[e*TT+idx] >> 1) : (g_list[e*TT] >> 1);
    }
    __syncthreads();

    const float* Bp = Bsrc + (mode>=1 ? (size_t)e*(size_t)K*(size_t)N : 0);
    int a_row = tid >> 1, a_h = (tid & 1) * 16;   // A: row, 16 k's
    int b_kr = tid >> 3, b_c = (tid & 7) * 16;    // B: k-row 0..31, 16 n's
    int wm = wid & 3, wn = wid >> 2;              // warp: M strip (32), N strip (64)

    wmma::fragment<wmma::accumulator,16,16,16,float> acc[2][4];
    #pragma unroll
    for (int i=0;i<2;i++)
        #pragma unroll
        for (int j=0;j<4;j++) wmma::fill_fragment(acc[i][j], 0.f);

    float4 pa[4], pb[4];
    // ---- global fetch of chunk k0 into regs ----
    auto fetch = [&](int k0){
        #pragma unroll
        for (int ii=0; ii<4; ii++) {
            int kk = a_h + 4*ii;
            if (mode==0) {
                pa[ii] = *(const float4*)(A + (size_t)(by+a_row)*K + k0 + kk);
            } else if (mode==1) {
                pa[ii] = *(const float4*)(g_h2 + (size_t)rows_s[a_row]*HH + k0 + kk);
            } else {
                size_t base = ((size_t)e*TT + by + a_row)*II + k0 + kk;
                float4 g4 = *(const float4*)(g_gbuf + base);
                float4 u4 = *(const float4*)(g_ubuf + base);
                pa[ii] = make_float4(g4.x*u4.x, g4.y*u4.y, g4.z*u4.z, g4.w*u4.w);
            }
        }
        #pragma unroll
        for (int ii=0; ii<4; ii++) {
            pb[ii] = *(const float4*)(Bp + (size_t)(k0+b_kr)*N + bx + b_c + 4*ii);
        }
    };
    // ---- convert regs -> smem buffer b ----
    auto stash = [&](int b){
        char* base = smc + b*BUF_SZ;
        __nv_bfloat16* Ahi = (__nv_bfloat16*)(base);
        __nv_bfloat16* Alo = (__nv_bfloat16*)(base + 10240);
        __nv_bfloat16* Bhi = (__nv_bfloat16*)(base + 20480);
        __nv_bfloat16* Blo = (__nv_bfloat16*)(base + 29184);
        #pragma unroll
        for (int ii=0; ii<4; ii++) {
            float4 v = pa[ii];
            __nv_bfloat16 h0,h1,h2,h3,l0,l1,l2,l3;
            split_bf16(v.x,h0,l0); split_bf16(v.y,h1,l1);
            split_bf16(v.z,h2,l2); split_bf16(v.w,h3,l3);
            int idx = a_row*A_LD + a_h + 4*ii;
            __nv_bfloat162* ph = (__nv_bfloat162*)&Ahi[idx];
            __nv_bfloat162* pl = (__nv_bfloat162*)&Alo[idx];
            ph[0] = __nv_bfloat162(h0,h1); ph[1] = __nv_bfloat162(h2,h3);
            pl[0] = __nv_bfloat162(l0,l1); pl[1] = __nv_bfloat162(l2,l3);
        }
        #pragma unroll
        for (int ii=0; ii<4; ii++) {
            float4 v = pb[ii];
            __nv_bfloat16 h0,h1,h2,h3,l0,l1,l2,l3;
            split_bf16(v.x,h0,l0); split_bf16(v.y,h1,l1);
            split_bf16(v.z,h2,l2); split_bf16(v.w,h3,l3);
            int idx = b_kr*B_LD + b_c + 4*ii;
            __nv_bfloat162* ph = (__nv_bfloat162*)&Bhi[idx];
            __nv_bfloat162* pl = (__nv_bfloat162*)&Blo[idx];
            ph[0] = __nv_bfloat162(h0,h1); ph[1] = __nv_bfloat162(h2,h3);
            pl[0] = __nv_bfloat162(l0,l1); pl[1] = __nv_bfloat162(l2,l3);
        }
    };

    int nch = K / KC;
    fetch(0);
    stash(0);
    __syncthreads();
    for (int c = 0; c < nch; c++) {
        int cur = c & 1, nxt = cur ^ 1;
        if (c+1 < nch) fetch((c+1)*KC);
        {
            char* base = smc + cur*BUF_SZ;
            __nv_bfloat16* Ahi = (__nv_bfloat16*)(base);
            __nv_bfloat16* Alo = (__nv_bfloat16*)(base + 10240);
            __nv_bfloat16* Bhi = (__nv_bfloat16*)(base + 20480);
            __nv_bfloat16* Blo = (__nv_bfloat16*)(base + 29184);
            #pragma unroll
            for (int kk=0; kk<2; kk++) {
                wmma::fragment<wmma::matrix_a,16,16,16,__nv_bfloat16,wmma::row_major> ah[2], al[2];
                wmma::fragment<wmma::matrix_b,16,16,16,__nv_bfloat16,wmma::row_major> bh[4], bl[4];
                #pragma unroll
                for (int i=0;i<2;i++) {
                    wmma::load_matrix_sync(ah[i], &Ahi[(wm*32 + i*16)*A_LD + kk*16], A_LD);
                    wmma::load_matrix_sync(al[i], &Alo[(wm*32 + i*16)*A_LD + kk*16], A_LD);
                }
                #pragma unroll
                for (int j=0;j<4;j++) {
                    wmma::load_matrix_sync(bh[j], &Bhi[(kk*16)*B_LD + wn*64 + j*16], B_LD);
                    wmma::load_matrix_sync(bl[j], &Blo[(kk*16)*B_LD + wn*64 + j*16], B_LD);
                }
                #pragma unroll
                for (int i=0;i<2;i++)
                    #pragma unroll
                    for (int j=0;j<4;j++) {
                        wmma::mma_sync(acc[i][j], ah[i], bh[j], acc[i][j]);
                        wmma::mma_sync(acc[i][j], ah[i], bl[j], acc[i][j]);
                        wmma::mma_sync(acc[i][j], al[i], bh[j], acc[i][j]);
                    }
            }
        }
        if (c+1 < nch) stash(nxt);
        __syncthreads();
    }
    // ---- store accumulators to fp32 staging (overlays tiles; safe after sync) ----
    #pragma unroll
    for (int i=0;i<2;i++)
        #pragma unroll
        for (int j=0;j<4;j++)
            wmma::store_matrix_sync(&stage[(wm*32 + i*16)*ST_LD + wn*64 + j*16],
                                    acc[i][j], ST_LD, wmma::mem_row_major);
    __syncthreads();
    // ---- guarded copy-out ----
    {
        int m_loc = tid >> 1, half = tid & 1;
        int m = by + m_loc;
        if (m < cnt) {
            const float* srow = stage + m_loc*ST_LD + half*64;
            float* dst;
            const float* ad = nullptr;
            int ng0 = bx + half*64;
            if (mode==0) {
                dst = Cdst + (size_t)m*N + ng0;
                if (addend) ad = addend + (size_t)m*N + ng0;
            } else if (mode==1) {
                dst = Cdst + ((size_t)e*TT + m)*N + ng0;
            } else {
                int entry = g_list[e*TT + m];
                dst = g_yslot + (size_t)entry*HH + ng0;
            }
            #pragma unroll
            for (int c4=0; c4<64; c4+=4) {
                float x0 = srow[c4+0], x1 = srow[c4+1], x2 = srow[c4+2], x3 = srow[c4+3];
                if (applySilu) {
                    x0 = x0/(1.f+expf(-x0)); x1 = x1/(1.f+expf(-x1));
                    x2 = x2/(1.f+expf(-x2)); x3 = x3/(1.f+expf(-x3));
                }
                if (ad) {
                    float4 a4 = *(const float4*)(ad + c4);
                    x0+=a4.x; x1+=a4.y; x2+=a4.z; x3+=a4.w;
                }
                *(float4*)(dst + c4) = make_float4(x0,x1,x2,x3);
            }
        }
    }
}

// ---------------- rmsnorm over 2048 ----------------
__global__ void rmsnorm_kernel(const float* __restrict__ x, const float* __restrict__ w,
                               float* __restrict__ out) {
    int t = blockIdx.x;
    const float* row = x + (size_t)t*HH;
    float ss = 0.f;
    for (int j = threadIdx.x; j < HH; j += 256) { float v = row[j]; ss += v*v; }
    __shared__ float sred[256];
    sred[threadIdx.x] = ss; __syncthreads();
    for (int s = 128; s > 0; s >>= 1) {
        if (threadIdx.x < s) sred[threadIdx.x] += sred[threadIdx.x+s];
        __syncthreads();
    }
    float scale = rsqrtf(sred[0]/(float)HH + EPSV);
    for (int j = threadIdx.x; j < HH; j += 256)
        out[(size_t)t*HH + j] = row[j]*scale*w[j];
}

// ---------------- per-(token,head) qk rmsnorm + rope; v copy ----------------
__global__ void qkv_post_kernel(const int* __restrict__ pos,
                                const float* __restrict__ wq, const float* __restrict__ wk) {
    int t = blockIdx.y;
    int slot = blockIdx.x;
    int d = threadIdx.x;
    const float* src;
    if (slot < 16)       src = g_qkv + (size_t)t*QKVN + slot*HD;
    else if (slot < 20)  src = g_qkv + (size_t)t*QKVN + 2048 + (slot-16)*HD;
    else                 src = g_qkv + (size_t)t*QKVN + 2560 + (slot-20)*HD;
    float v = src[d];
    if (slot >= 20) { g_v[(size_t)t*NKVH*HD + (slot-20)*HD + d] = v; return; }
    float x2 = v*v;
    #pragma unroll
    for (int o=16;o;o>>=1) x2 += __shfl_xor_sync(0xffffffffu, x2, o);
    __shared__ float wsum[4];
    if ((d&31)==0) wsum[d>>5] = x2;
    __syncthreads();
    float tot = wsum[0]+wsum[1]+wsum[2]+wsum[3];
    float scale = rsqrtf(tot/(float)HD + EPSV);
    const float* wn = (slot<16)? wq : wk;
    float xn = v * scale * wn[d];
    __shared__ float sh[128];
    sh[d] = xn; __syncthreads();
    int i = d & 63;
    float inv = expf(-(float)i * (logf(10000.0f)/64.0f));
    float ang = (float)pos[t] * inv;
    float c = cosf(ang), s = sinf(ang);
    float o;
    if (d < 64) o = sh[d]*c - sh[d+64]*s;
    else        o = sh[d]*c + sh[d-64]*s;
    if (slot < 16) g_q[(size_t)t*NHEAD*HD + slot*HD + d] = o * 0.08838834764831845f;
    else           g_k[(size_t)t*NKVH*HD + (slot-16)*HD + d] = o;
}

// ---------------- flash-style attention (R8 winner, unchanged) ----------------
#define QT_STRIDE 68
#define V_STRIDE  132
#define S_STRIDE  66
__global__ void __launch_bounds__(256) attn_kernel() {
    extern __shared__ float sm[];
    float* Qt   = sm;
    float* KV   = sm + 128*QT_STRIDE;
    float* S    = KV + 128*QT_STRIDE;
    float* mrow = S + 64*S_STRIDE;
    float* lrow = mrow + 64;
    float* arow = lrow + 64;
    int h = blockIdx.x, qt = blockIdx.y;
    int kvh = h >> 2;
    int tid = threadIdx.x;
    int r = tid >> 2, g = tid & 3;
    int tr = tid >> 4, tc = tid & 15;
    {
        const float4* src = (const float4*)(g_q + (size_t)(qt*64 + r)*HH + h*HD + g*32);
        #pragma unroll
        for (int i4=0;i4<8;i4++) {
            float4 v = src[i4];
            int db = g*32 + i4*4;
            Qt[(db+0)*QT_STRIDE + r] = v.x;
            Qt[(db+1)*QT_STRIDE + r] = v.y;
            Qt[(db+2)*QT_STRIDE + r] = v.z;
            Qt[(db+3)*QT_STRIDE + r] = v.w;
        }
    }
    if (tid < 64) { mrow[tid] = -1e30f; lrow[tid] = 0.f; }
    float O[4][8];
    #pragma unroll
    for (int i=0;i<4;i++)
        #pragma unroll
        for (int j=0;j<8;j++) O[i][j]=0.f;
    __syncthreads();
    for (int kt = 0; kt < 16; kt++) {
        {
            const float4* src = (const float4*)(g_k + (size_t)(kt*64 + r)*NKVH*HD + kvh*HD + g*32);
            #pragma unroll
            for (int i4=0;i4<8;i4++) {
                float4 v = src[i4];
                int db = g*32 + i4*4;
                KV[(db+0)*QT_STRIDE + r] = v.x;
                KV[(db+1)*QT_STRIDE + r] = v.y;
                KV[(db+2)*QT_STRIDE + r] = v.z;
                KV[(db+3)*QT_STRIDE + r] = v.w;
            }
        }
        __syncthreads();
        {
            float acc[4][4];
            #pragma unroll
            for (int i=0;i<4;i++)
                #pragma unroll
                for (int j=0;j<4;j++) acc[i][j]=0.f;
            #pragma unroll 4
            for (int d=0; d<HD; d++) {
                float4 a4 = *(const float4*)&Qt[d*QT_STRIDE + 4*tr];
                float4 b4 = *(const float4*)&KV[d*QT_STRIDE + 4*tc];
                float a[4] = {a4.x,a4.y,a4.z,a4.w};
                float b[4] = {b4.x,b4.y,b4.z,b4.w};
                #pragma unroll
                for (int i=0;i<4;i++)
                    #pragma unroll
                    for (int j=0;j<4;j++) acc[i][j] += a[i]*b[j];
            }
            #pragma unroll
            for (int i=0;i<4;i++)
                #pragma unroll
                for (int j=0;j<4;j++) S[(4*tr+i)*S_STRIDE + 4*tc+j] = acc[i][j];
        }
        __syncthreads();
        {
            float* Sr = S + r*S_STRIDE + g*16;
            float mloc = -1e30f;
            #pragma unroll
            for (int j=0;j<16;j++) mloc = fmaxf(mloc, Sr[j]);
            #pragma unroll
            for (int o=1;o<4;o<<=1) mloc = fmaxf(mloc, __shfl_xor_sync(0xffffffffu, mloc, o));
            float mold = mrow[r];
            float mnew = fmaxf(mold, mloc);
            float psum = 0.f;
            #pragma unroll
            for (int j=0;j<16;j++) { float pp = expf(Sr[j]-mnew); Sr[j]=pp; psum+=pp; }
            #pragma unroll
            for (int o=1;o<4;o<<=1) psum += __shfl_xor_sync(0xffffffffu, psum, o);
            if (g==0) {
                float alpha = expf(mold - mnew);
                arow[r] = alpha;
                mrow[r] = mnew;
                lrow[r] = lrow[r]*alpha + psum;
            }
            const float4* src = (const float4*)(g_v + (size_t)(kt*64 + r)*NKVH*HD + kvh*HD + g*32);
            float* dst = KV + r*V_STRIDE + g*32;
            #pragma unroll
            for (int i4=0;i4<8;i4++) *(float4*)(dst + i4*4) = src[i4];
        }
        __syncthreads();
        {
            float al[4];
            #pragma unroll
            for (int i=0;i<4;i++) al[i] = arow[4*tr+i];
            #pragma unroll
            for (int i=0;i<4;i++)
                #pragma unroll
                for (int j=0;j<8;j++) O[i][j]*=al[i];
            for (int kk=0; kk<64; kk++) {
                float4 b0 = *(const float4*)&KV[kk*V_STRIDE + tc*8];
                float4 b1 = *(const float4*)&KV[kk*V_STRIDE + tc*8 + 4];
                float b[8] = {b0.x,b0.y,b0.z,b0.w,b1.x,b1.y,b1.z,b1.w};
                #pragma unroll
                for (int i=0;i<4;i++) {
                    float pv = S[(4*tr+i)*S_STRIDE + kk];
                    #pragma unroll
                    for (int j=0;j<8;j++) O[i][j] += pv*b[j];
                }
            }
        }
        __syncthreads();
    }
    #pragma unroll
    for (int i=0;i<4;i++) {
        int row = 4*tr+i;
        float linv = 1.0f / lrow[row];
        float* dst = g_ctx + (size_t)(qt*64+row)*HH + h*HD + tc*8;
        #pragma unroll
        for (int j=0;j<8;j++) dst[j] = O[i][j]*linv;
    }
}

// ---------------- router ----------------
__global__ void router_kernel(const float* __restrict__ wr) {
    int t = blockIdx.x;
    float acc[NEXP];
    #pragma unroll
    for (int e=0;e<NEXP;e++) acc[e]=0.f;
    for (int j=threadIdx.x; j<HH; j+=256) {
        float x = g_h2[(size_t)t*HH+j];
        const float* w = wr + j*NEXP;
        #pragma unroll
        for (int e=0;e<NEXP;e++) acc[e] += x*w[e];
    }
    __shared__ float sred[256];
    __shared__ float logits[NEXP];
    for (int e=0;e<NEXP;e++) {
        sred[threadIdx.x]=acc[e]; __syncthreads();
        for (int s=128;s>0;s>>=1){ if(threadIdx.x<s) sred[threadIdx.x]+=sred[threadIdx.x+s]; __syncthreads(); }
        if (threadIdx.x==0) logits[e]=sred[0];
        __syncthreads();
    }
    if (threadIdx.x==0) {
        int i1=0; float l1=logits[0];
        for (int e=1;e<NEXP;e++) if (logits[e]>l1){l1=logits[e]; i1=e;}
        int i2=-1; float l2=-1e30f;
        for (int e=0;e<NEXP;e++) if (e!=i1 && logits[e]>l2){l2=logits[e]; i2=e;}
        float w1 = 1.0f/(1.0f+expf(l2-l1));
        g_topi[2*t]=i1; g_topi[2*t+1]=i2;
        g_topw[2*t]=w1; g_topw[2*t+1]=1.0f-w1;
    }
}

// ---------------- deterministic per-expert compaction ----------------
__global__ void build_lists_kernel() {
    int e = blockIdx.x;
    int t = threadIdx.x;
    int slot = -1;
    if (g_topi[2*t]==e) slot=0; else if (g_topi[2*t+1]==e) slot=1;
    int flag = (slot>=0) ? 1 : 0;
    unsigned mask = __ballot_sync(0xffffffffu, flag);
    int lane = t & 31, warp = t >> 5;
    int pos = __popc(mask & ((1u<<lane)-1u));
    __shared__ int wsum[32];
    if (lane==0) wsum[warp]=__popc(mask);
    __syncthreads();
    if (t < 32) {
        int v = wsum[t];
        #pragma unroll
        for (int o=1;o<32;o<<=1){ int n=__shfl_up_sync(0xffffffffu, v, o); if (t>=o) v+=n; }
        wsum[t]=v;
    }
    __syncthreads();
    int base = (warp==0) ? 0 : wsum[warp-1];
    if (flag) g_list[e*TT + base + pos] = 2*t+slot;
    if (t==0) g_count[e]=wsum[31];
}

// ---------------- final combine ----------------
__global__ void combine_kernel(float* __restrict__ out) {
    int t = blockIdx.x;
    float w0 = g_topw[2*t], w1 = g_topw[2*t+1];
    const float* y0 = g_yslot + (size_t)(2*t)*HH;
    const float* y1 = y0 + HH;
    float* o = out + (size_t)t*HH;
    for (int j=threadIdx.x;j<HH;j+=256) o[j] = w0*y0[j] + w1*y1[j];
}

// ---------------- launch ----------------
extern "C" void kernel_launch(void* const* d_in, const int* in_sizes, int n_in,
                              void* d_out, int out_size) {
    const float* hidden   = (const float*)d_in[0];
    const int*   pos      = (const int*)  d_in[1];
    const float* w_norm1  = (const float*)d_in[2];
    const float* w_norm2  = (const float*)d_in[3];
    const float* w_qkv    = (const float*)d_in[4];
    const float* w_qnorm  = (const float*)d_in[5];
    const float* w_knorm  = (const float*)d_in[6];
    const float* w_o      = (const float*)d_in[7];
    const float* w_router = (const float*)d_in[8];
    const float* w_gate   = (const float*)d_in[9];
    const float* w_up     = (const float*)d_in[10];
    const float* w_down   = (const float*)d_in[11];
    (void)in_sizes; (void)n_in; (void)out_size;

    float* moe_out = (float*)d_out;
    float* resid   = (float*)d_out + (size_t)TT*HH;

    void* p;
    cudaGetSymbolAddress(&p, g_h1);   float* h1   = (float*)p;
    cudaGetSymbolAddress(&p, g_qkv);  float* qkv  = (float*)p;
    cudaGetSymbolAddress(&p, g_ctx);  float* ctx  = (float*)p;
    cudaGetSymbolAddress(&p, g_h2);   float* h2   = (float*)p;
    cudaGetSymbolAddress(&p, g_gbuf); float* gbuf = (float*)p;
    cudaGetSymbolAddress(&p, g_ubuf); float* ubuf = (float*)p;

    int attn_smem = (128*QT_STRIDE*2 + 64*S_STRIDE + 192) * 4;
    cudaFuncSetAttribute(attn_kernel, cudaFuncAttributeMaxDynamicSharedMemorySize, attn_smem);
    cudaFuncSetAttribute(wg_gemm_kernel, cudaFuncAttributeMaxDynamicSharedMemorySize, WG_SMEM);

    rmsnorm_kernel<<<TT, 256>>>(hidden, w_norm1, h1);
    wg_gemm_kernel<<<dim3(QKVN/128, TT/128, 1), 256, WG_SMEM>>>(h1, w_qkv, qkv, QKVN, HH, nullptr, 0, 0);
    qkv_post_kernel<<<dim3(24, TT), 128>>>(pos, w_qnorm, w_knorm);
    attn_kernel<<<dim3(NHEAD, TT/64), 256, attn_smem>>>();
    wg_gemm_kernel<<<dim3(HH/128, TT/128, 1), 256, WG_SMEM>>>(ctx, w_o, resid, HH, HH, hidden, 0, 0);
    rmsnorm_kernel<<<TT, 256>>>(resid, w_norm2, h2);
    router_kernel<<<TT, 256>>>(w_router);
    build_lists_kernel<<<NEXP, TT>>>();
    wg_gemm_kernel<<<dim3(II/128, TT/128, NEXP), 256, WG_SMEM>>>(nullptr, w_gate, gbuf, II, HH, nullptr, 1, 1);
    wg_gemm_kernel<<<dim3(II/128, TT/128, NEXP), 256, WG_SMEM>>>(nullptr, w_up,   ubuf, II, HH, nullptr, 1, 0);
    wg_gemm_kernel<<<dim3(HH/128, TT/128, NEXP), 256, WG_SMEM>>>(nullptr, w_down, nullptr, HH, II, nullptr, 2, 0);
    combine_kernel<<<TT, 256>>>(moe_out);
}